// round 10
// baseline (speedup 1.0000x reference)
#include <cuda_runtime.h>
#include <cstdint>

// FactorizedSpectralConv on GB300 — radix-2 folded direct DFTs (R8 base).
// R10: g_Y transposed to [bc][m] (coalesced inverse loads); inverse phase B
// does 2 w-values x 4 rows per thread (33% fewer LDS instructions).
// B=16, C=64, H=W=128, M0=M1=16.

typedef unsigned long long ull;
#define PI2_OVER_128 0.04908738521234051935f  // 2*pi/128
#define SGN2 0x8000000080000000ULL

// Scratch (device globals; allocation-free rule)
__device__ float2 g_Xf[512 * 1024];   // [m][t*16+b], 4 MB
__device__ float2 g_Y [1024 * 512];   // [b*64+c][m], 4 MB (transposed!)
__device__ float2 g_W [512 * 4096];   // [m][c*64+t], 16 MB (transposed weights)

__device__ __forceinline__ ull pk2(float x, float y) {
    ull r; asm("mov.b64 %0,{%1,%2};" : "=l"(r) : "f"(x), "f"(y)); return r;
}
__device__ __forceinline__ void upk2(ull v, float& x, float& y) {
    asm("mov.b64 {%0,%1},%2;" : "=f"(x), "=f"(y) : "l"(v));
}
__device__ __forceinline__ void fma2(ull& d, ull a, ull b) {
    asm("fma.rn.f32x2 %0,%1,%2,%0;" : "+l"(d) : "l"(a), "l"(b));
}
__device__ __forceinline__ ull add2(ull a, ull b) {
    ull d; asm("add.rn.f32x2 %0,%1,%2;" : "=l"(d) : "l"(a), "l"(b)); return d;
}
__device__ __forceinline__ ull sub2(ull a, ull b) {
    return add2(a, b ^ SGN2);
}

// ---- compile-time trig (double Taylor, |x| <= pi, err ~1e-11) ----
constexpr double PI_D = 3.14159265358979323846264338327950288;
__host__ __device__ constexpr double tsin_(double x) {
    double t = x, s = x, x2 = x * x;
    for (int i = 1; i <= 12; i++) { t *= -x2 / double((2 * i) * (2 * i + 1)); s += t; }
    return s;
}
__host__ __device__ constexpr double tcos_(double x) {
    double t = 1.0, s = 1.0, x2 = x * x;
    for (int i = 1; i <= 12; i++) { t *= -x2 / double((2 * i - 1) * (2 * i)); s += t; }
    return s;
}
__host__ __device__ constexpr float TWC(int w, int k) {   // cos/16384
    int n = (w * k) & 127;
    double x = (2.0 * PI_D * n) / 128.0;
    if (n > 64) x -= 2.0 * PI_D;
    return (float)(tcos_(x) / 16384.0);
}
__host__ __device__ constexpr float TWS(int w, int k) {   // -sin/16384
    int n = (w * k) & 127;
    double x = (2.0 * PI_D * n) / 128.0;
    if (n > 64) x -= 2.0 * PI_D;
    return (float)(-tsin_(x) / 16384.0);
}

// ---- templated phase-A MAC ladder: all twiddles become FFMA immediates ----
template <int W, int K = 0>
__device__ __forceinline__ void rowA(float xp, float xm, float* ar, float* ai) {
    if constexpr (K < 16) {
        constexpr float c = TWC(W, K);
        constexpr float s = TWS(W, K);
        float x = (K & 1) ? xm : xp;
        ar[K] = fmaf(x, c, ar[K]);
        ai[K] = fmaf(x, s, ai[K]);
        rowA<W, K + 1>(xp, xm, ar, ai);
    }
}
template <int C0, int W2 = 0>
__device__ __forceinline__ void chunkA(const float2 (*Xs2)[17], int tid,
                                       float* ar, float* ai) {
    if constexpr (W2 < 16) {
        float2 xv = Xs2[tid][W2];
        rowA<C0 + W2>(xv.x + xv.y, xv.x - xv.y, ar, ai);
        chunkA<C0, W2 + 1>(Xs2, tid, ar, ai);
    }
}

// ---------------------------------------------------------------------------
// K0: weight transpose  w[c][t][kx0][ky] (stride-256 cols) -> g_W[m][c*64+t]
// ---------------------------------------------------------------------------
__global__ void __launch_bounds__(256) k_transpose(
    const float* __restrict__ w0r, const float* __restrict__ w0i,
    const float* __restrict__ w1r, const float* __restrict__ w1i) {
    __shared__ float Tr[32][33], Ti[32][33];
    int bid = blockIdx.x;
    int arr = bid >> 10;
    int tix = bid & 1023;
    int ctTile = tix >> 3, mTile = tix & 7;
    const float* Sr = arr ? w1r : w0r;
    const float* Si = arr ? w1i : w0i;
    int tx = threadIdx.x & 31, ty = threadIdx.x >> 5;
    #pragma unroll
    for (int yy = 0; yy < 4; yy++) {
        int r = ty + yy * 8;
        int row = ctTile * 32 + r, col = mTile * 32 + tx;
        Tr[r][tx] = Sr[row * 256 + col];
        Ti[r][tx] = Si[row * 256 + col];
    }
    __syncthreads();
    #pragma unroll
    for (int yy = 0; yy < 4; yy++) {
        int r = ty + yy * 8;
        int m = arr * 256 + mTile * 32 + r;
        int ct = ctTile * 32 + tx;
        g_W[(size_t)m * 4096 + ct] = make_float2(Tr[tx][r], Ti[tx][r]);
    }
}

// ---------------------------------------------------------------------------
// K1: forward. grid = 1024 blocks, 128 threads, Xs2/Fw smem overlay.
// ---------------------------------------------------------------------------
__global__ void __launch_bounds__(128, 8) k_forward(const float* __restrict__ X) {
    __shared__ __align__(16) ull TWB[128][2];   // (c,-s),(s,c) — 2KB
    __shared__ __align__(16) char u_smem[17408];  // Xs2 / Fw overlay
    float2 (*Xs2)[17] = (float2(*)[17])u_smem;
    ull    (*Fw)[129] = (ull(*)[129])u_smem;

    int tid = threadIdx.x;
    {
        float s, c; sincosf(PI2_OVER_128 * (float)tid, &s, &c);
        TWB[tid][0] = pk2(c, -s);
        TWB[tid][1] = pk2(s, c);
    }

    const float* Xp = X + (size_t)blockIdx.x * 16384;

    float ar[16], ai[16];
    #pragma unroll
    for (int k = 0; k < 16; k++) { ar[k] = 0.f; ai[k] = 0.f; }

    #pragma unroll 1
    for (int c0 = 0; c0 < 64; c0 += 16) {
        __syncthreads();
        #pragma unroll
        for (int p = 0; p < 8; p++) {
            int i = p * 128 + tid;
            int r = i >> 3, q = i & 7;
            const float* src = (q < 4) ? (Xp + r * 128 + c0 + q * 4)
                                       : (Xp + r * 128 + c0 + 64 + (q - 4) * 4);
            float4 v = *(const float4*)src;
            if (q < 4) {
                Xs2[r][q * 4 + 0].x = v.x; Xs2[r][q * 4 + 1].x = v.y;
                Xs2[r][q * 4 + 2].x = v.z; Xs2[r][q * 4 + 3].x = v.w;
            } else {
                Xs2[r][(q - 4) * 4 + 0].y = v.x; Xs2[r][(q - 4) * 4 + 1].y = v.y;
                Xs2[r][(q - 4) * 4 + 2].y = v.z; Xs2[r][(q - 4) * 4 + 3].y = v.w;
            }
        }
        __syncthreads();
        switch (c0) {
            case 0:  chunkA<0 >(Xs2, tid, ar, ai); break;
            case 16: chunkA<16>(Xs2, tid, ar, ai); break;
            case 32: chunkA<32>(Xs2, tid, ar, ai); break;
            default: chunkA<48>(Xs2, tid, ar, ai); break;
        }
    }

    __syncthreads();
    #pragma unroll
    for (int k = 0; k < 16; k++) Fw[k][tid] = pk2(ar[k], ai[k]);
    __syncthreads();

    int ky = tid & 15, kxg = tid >> 4;
    ull accB[4] = {0, 0, 0, 0}, accC[4] = {0, 0, 0, 0};
    int kxv[4], idx[4];
    #pragma unroll
    for (int j = 0; j < 4; j++) {
        int kxIdx = kxg * 4 + j;
        kxv[j] = (kxIdx < 16) ? kxIdx : (96 + kxIdx);
        idx[j] = 0;
    }
    for (int h = 0; h < 64; h++) {
        ull a = Fw[ky][h], b = Fw[ky][h + 64];
        ull p = add2(a, b), m = sub2(a, b);
        float pr, pi, mr, mi;
        upk2(p, pr, pi); upk2(m, mr, mi);
        ull prr = pk2(pr, pr), pii = pk2(pi, pi);
        ull mrr = pk2(mr, mr), mii = pk2(mi, mi);
        #pragma unroll
        for (int j = 0; j < 4; j++) {
            ulonglong2 e = *(const ulonglong2*)&TWB[idx[j]][0];
            if (j & 1) { fma2(accB[j], mrr, e.x); fma2(accC[j], mii, e.y); }
            else       { fma2(accB[j], prr, e.x); fma2(accC[j], pii, e.y); }
            idx[j] = (idx[j] + kxv[j]) & 127;
        }
    }
    int b = blockIdx.x >> 6, t = blockIdx.x & 63;
    #pragma unroll
    for (int j = 0; j < 4; j++) {
        int m = (kxg * 4 + j) * 16 + ky;
        ull r = add2(accB[j], accC[j]);
        float re, im; upk2(r, re, im);
        g_Xf[m * 1024 + t * 16 + b] = make_float2(re, im);
    }
}

// ---------------------------------------------------------------------------
// K2: mode mixing. grid = 512, 256 threads. Writes g_Y transposed [bc][m].
// ---------------------------------------------------------------------------
__global__ void __launch_bounds__(256) k_modes() {
    extern __shared__ __align__(16) char sm2[];
    ulonglong2* Wsp = (ulonglong2*)sm2;                          // [64 t][65]
    ulonglong2* Xsm = (ulonglong2*)(sm2 + 64 * 65 * 16);         // [64 t][16 b]
    ull*        Ys2 = (ull*)(sm2 + 64 * 65 * 16 + 64 * 16 * 16); // [1024]

    int m = blockIdx.x, tid = threadIdx.x;

    #pragma unroll
    for (int p = 0; p < 16; p++) {
        int i = tid + p * 256;
        float2 w = g_W[(size_t)m * 4096 + i];
        Wsp[(i & 63) * 65 + (i >> 6)] = make_ulonglong2(pk2(w.x, w.x), pk2(w.y, w.y));
    }
    #pragma unroll
    for (int p = 0; p < 4; p++) {
        int i = tid + p * 256;
        float2 x = g_Xf[m * 1024 + i];
        Xsm[i] = make_ulonglong2(pk2(x.x, x.y), pk2(-x.y, x.x));
    }
    __syncthreads();

    int b = tid & 15, cq = tid >> 4;
    ull acc[4] = {0, 0, 0, 0};
    for (int t = 0; t < 64; t++) {
        ulonglong2 xv = Xsm[t * 16 + b];
        #pragma unroll
        for (int j = 0; j < 4; j++) {
            ulonglong2 wv = Wsp[t * 65 + cq * 4 + j];
            fma2(acc[j], wv.x, xv.x);
            fma2(acc[j], wv.y, xv.y);
        }
    }
    #pragma unroll
    for (int j = 0; j < 4; j++) Ys2[b * 64 + cq * 4 + j] = acc[j];
    __syncthreads();
    // Scattered (stride-512 float2) writes into transposed g_Y[bc][m];
    // fire-and-forget STG, absorbed by L2.
    #pragma unroll
    for (int p = 0; p < 4; p++) {
        int i = tid + p * 256;
        *(ull*)&g_Y[(size_t)i * 512 + m] = Ys2[i];
    }
}

// ---------------------------------------------------------------------------
// K3: inverse. grid = 1024 blocks, 256 threads, <=64 regs -> 4 blocks/SM.
// Radix-2 fold in kx parity (phase A) and ky parity (phase B).
// Phase B: 2 w-values x 4 rows per thread.
// ---------------------------------------------------------------------------
__global__ void __launch_bounds__(256, 4) k_inverse(float* __restrict__ out) {
    __shared__ __align__(16) ull TWI[128][2];       // (c,s),(-s,c) — 2KB
    __shared__ __align__(16) ulonglong2 TWIB[128];  // ((2c,2c),(-2s,-2s)) — 2KB
    __shared__ ull Ysm[512];                        // 4KB
    __shared__ __align__(16) ulonglong2 ZZ[64][17]; // [(zr_h,zr_h64),(zi_h,zi_h64)]

    int tid = threadIdx.x;
    if (tid < 128) {
        float s, c; sincosf(PI2_OVER_128 * (float)tid, &s, &c);
        TWI[tid][0] = pk2(c, s);
        TWI[tid][1] = pk2(-s, c);
        TWIB[tid] = make_ulonglong2(pk2(2.f * c, 2.f * c), pk2(-2.f * s, -2.f * s));
    }
    int off = blockIdx.x;   // b*64 + c
    // Coalesced: 256 threads x 16B cover the 512-ull row g_Y[off][0..511].
    ((ulonglong2*)Ysm)[tid] = *(const ulonglong2*)&g_Y[(size_t)off * 512 + tid * 2];
    __syncthreads();

    // Phase A: Z[h] = Se+So, Z[h+64] = Se-So. Thread: h in {hq,hq+16,hq+32,hq+48}.
    {
        int ky = tid & 15, hq = tid >> 4;          // hq in 0..15
        ull Se[4] = {0, 0, 0, 0}, So[4] = {0, 0, 0, 0};
        int idx[4] = {0, 0, 0, 0};

        #pragma unroll
        for (int kxI = 0; kxI < 16; kxI++) {       // kx = kxI
            float yr, yi; upk2(Ysm[kxI * 16 + ky], yr, yi);
            ull yrr = pk2(yr, yr), yii = pk2(yi, yi);
            #pragma unroll
            for (int u = 0; u < 4; u++) {
                ulonglong2 e = *(const ulonglong2*)&TWI[idx[u]][0];
                if (kxI & 1) { fma2(So[u], yrr, e.x); fma2(So[u], yii, e.y); }
                else         { fma2(Se[u], yrr, e.x); fma2(Se[u], yii, e.y); }
                idx[u] = (idx[u] + hq + 16 * u) & 127;
            }
        }
        #pragma unroll
        for (int u = 0; u < 4; u++) idx[u] = (112 * (hq + 16 * u)) & 127;
        #pragma unroll
        for (int kxI = 16; kxI < 32; kxI++) {      // kx = 96+kxI, same parity
            float yr, yi; upk2(Ysm[kxI * 16 + ky], yr, yi);
            ull yrr = pk2(yr, yr), yii = pk2(yi, yi);
            #pragma unroll
            for (int u = 0; u < 4; u++) {
                ulonglong2 e = *(const ulonglong2*)&TWI[idx[u]][0];
                if (kxI & 1) { fma2(So[u], yrr, e.x); fma2(So[u], yii, e.y); }
                else         { fma2(Se[u], yrr, e.x); fma2(Se[u], yii, e.y); }
                idx[u] = (idx[u] + hq + 16 * u) & 127;
            }
        }
        #pragma unroll
        for (int u = 0; u < 4; u++) {
            int r = hq + 16 * u;
            ull zp = add2(Se[u], So[u]);   // h = r
            ull zm = sub2(Se[u], So[u]);   // h = r + 64
            float pr, pi, mr, mi;
            upk2(zp, pr, pi); upk2(zm, mr, mi);
            ZZ[r][ky] = make_ulonglong2(pk2(pr, mr), pk2(pi, mi));
        }
    }
    __syncthreads();

    // Phase B: thread (wl, rg) handles w in {wl, wl+32} (each +64 via parity)
    // for 4 rows per pass, 2 passes. 16 ull accumulators.
    int wl = tid & 31, rg = tid >> 5;      // rg in 0..7
    float* op = out + (size_t)blockIdx.x * 16384;
    #pragma unroll 1
    for (int pass = 0; pass < 2; pass++) {
        int r0 = rg * 4 + pass * 32;
        ull E1[4], O1[4], E2[4], O2[4];
        #pragma unroll
        for (int i = 0; i < 4; i++) {
            ull z0 = ZZ[r0 + i][0].x;      // ky=0: Re(Z0), weight 1
            E1[i] = z0; O1[i] = 0;
            E2[i] = z0; O2[i] = 0;
        }
        int a1 = wl, a2 = wl + 32;
        #pragma unroll
        for (int k = 1; k < 16; k++) {
            ulonglong2 e1 = TWIB[a1];
            ulonglong2 e2 = TWIB[a2];
            if (k & 1) {
                #pragma unroll
                for (int i = 0; i < 4; i++) {
                    ulonglong2 zz = ZZ[r0 + i][k];
                    fma2(O1[i], zz.x, e1.x); fma2(O1[i], zz.y, e1.y);
                    fma2(O2[i], zz.x, e2.x); fma2(O2[i], zz.y, e2.y);
                }
            } else {
                #pragma unroll
                for (int i = 0; i < 4; i++) {
                    ulonglong2 zz = ZZ[r0 + i][k];
                    fma2(E1[i], zz.x, e1.x); fma2(E1[i], zz.y, e1.y);
                    fma2(E2[i], zz.x, e2.x); fma2(E2[i], zz.y, e2.y);
                }
            }
            a1 = (a1 + wl) & 127;
            a2 = (a2 + wl + 32) & 127;
        }
        #pragma unroll
        for (int i = 0; i < 4; i++) {
            int r = r0 + i;
            ull oa = add2(E1[i], O1[i]);   // w = wl
            ull ob = sub2(E1[i], O1[i]);   // w = wl + 64
            ull oc = add2(E2[i], O2[i]);   // w = wl + 32
            ull od = sub2(E2[i], O2[i]);   // w = wl + 96
            float a0, a64, b0, b64, c0, c64, d0, d64;
            upk2(oa, a0, a64); upk2(ob, b0, b64);
            upk2(oc, c0, c64); upk2(od, d0, d64);
            op[r * 128 + wl]             = a0;
            op[(r + 64) * 128 + wl]      = a64;
            op[r * 128 + wl + 64]        = b0;
            op[(r + 64) * 128 + wl + 64] = b64;
            op[r * 128 + wl + 32]        = c0;
            op[(r + 64) * 128 + wl + 32] = c64;
            op[r * 128 + wl + 96]        = d0;
            op[(r + 64) * 128 + wl + 96] = d64;
        }
    }
}

// ---------------------------------------------------------------------------
extern "C" void kernel_launch(void* const* d_in, const int* in_sizes, int n_in,
                              void* d_out, int out_size) {
    const float* X   = (const float*)d_in[0];
    const float* w0r = (const float*)d_in[1];
    const float* w0i = (const float*)d_in[2];
    const float* w1r = (const float*)d_in[3];
    const float* w1i = (const float*)d_in[4];
    float* out = (float*)d_out;

    static bool attr_done = false;
    if (!attr_done) {
        cudaFuncSetAttribute(k_modes, cudaFuncAttributeMaxDynamicSharedMemorySize,
                             91136);
        attr_done = true;
    }

    k_transpose<<<2048, 256>>>(w0r, w0i, w1r, w1i);
    k_forward<<<1024, 128>>>(X);
    k_modes<<<512, 256, 91136>>>();
    k_inverse<<<1024, 256>>>(out);
}

// round 11
// speedup vs baseline: 1.0231x; 1.0231x over previous
#include <cuda_runtime.h>
#include <cstdint>

// FactorizedSpectralConv on GB300 — radix-2 folded direct DFTs (R8 base).
// R11: R8 memory layouts restored; k_inverse phase B does 2 w-values x 4 rows
// per thread (fewer LDS per FMA, same registers/stores).
// B=16, C=64, H=W=128, M0=M1=16.

typedef unsigned long long ull;
#define PI2_OVER_128 0.04908738521234051935f  // 2*pi/128
#define SGN2 0x8000000080000000ULL

// Scratch (device globals; allocation-free rule)
__device__ float2 g_Xf[512 * 1024];   // [m][t*16+b], 4 MB
__device__ float2 g_Y [512 * 1024];   // [m][b*64+c], 4 MB
__device__ float2 g_W [512 * 4096];   // [m][c*64+t], 16 MB (transposed weights)

__device__ __forceinline__ ull pk2(float x, float y) {
    ull r; asm("mov.b64 %0,{%1,%2};" : "=l"(r) : "f"(x), "f"(y)); return r;
}
__device__ __forceinline__ void upk2(ull v, float& x, float& y) {
    asm("mov.b64 {%0,%1},%2;" : "=f"(x), "=f"(y) : "l"(v));
}
__device__ __forceinline__ void fma2(ull& d, ull a, ull b) {
    asm("fma.rn.f32x2 %0,%1,%2,%0;" : "+l"(d) : "l"(a), "l"(b));
}
__device__ __forceinline__ ull add2(ull a, ull b) {
    ull d; asm("add.rn.f32x2 %0,%1,%2;" : "=l"(d) : "l"(a), "l"(b)); return d;
}
__device__ __forceinline__ ull sub2(ull a, ull b) {
    return add2(a, b ^ SGN2);
}

// ---- compile-time trig (double Taylor, |x| <= pi, err ~1e-11) ----
constexpr double PI_D = 3.14159265358979323846264338327950288;
__host__ __device__ constexpr double tsin_(double x) {
    double t = x, s = x, x2 = x * x;
    for (int i = 1; i <= 12; i++) { t *= -x2 / double((2 * i) * (2 * i + 1)); s += t; }
    return s;
}
__host__ __device__ constexpr double tcos_(double x) {
    double t = 1.0, s = 1.0, x2 = x * x;
    for (int i = 1; i <= 12; i++) { t *= -x2 / double((2 * i - 1) * (2 * i)); s += t; }
    return s;
}
__host__ __device__ constexpr float TWC(int w, int k) {   // cos/16384
    int n = (w * k) & 127;
    double x = (2.0 * PI_D * n) / 128.0;
    if (n > 64) x -= 2.0 * PI_D;
    return (float)(tcos_(x) / 16384.0);
}
__host__ __device__ constexpr float TWS(int w, int k) {   // -sin/16384
    int n = (w * k) & 127;
    double x = (2.0 * PI_D * n) / 128.0;
    if (n > 64) x -= 2.0 * PI_D;
    return (float)(-tsin_(x) / 16384.0);
}

// ---- templated phase-A MAC ladder: all twiddles become FFMA immediates ----
template <int W, int K = 0>
__device__ __forceinline__ void rowA(float xp, float xm, float* ar, float* ai) {
    if constexpr (K < 16) {
        constexpr float c = TWC(W, K);
        constexpr float s = TWS(W, K);
        float x = (K & 1) ? xm : xp;
        ar[K] = fmaf(x, c, ar[K]);
        ai[K] = fmaf(x, s, ai[K]);
        rowA<W, K + 1>(xp, xm, ar, ai);
    }
}
template <int C0, int W2 = 0>
__device__ __forceinline__ void chunkA(const float2 (*Xs2)[17], int tid,
                                       float* ar, float* ai) {
    if constexpr (W2 < 16) {
        float2 xv = Xs2[tid][W2];
        rowA<C0 + W2>(xv.x + xv.y, xv.x - xv.y, ar, ai);
        chunkA<C0, W2 + 1>(Xs2, tid, ar, ai);
    }
}

// ---------------------------------------------------------------------------
// K0: weight transpose  w[c][t][kx0][ky] (stride-256 cols) -> g_W[m][c*64+t]
// ---------------------------------------------------------------------------
__global__ void __launch_bounds__(256) k_transpose(
    const float* __restrict__ w0r, const float* __restrict__ w0i,
    const float* __restrict__ w1r, const float* __restrict__ w1i) {
    __shared__ float Tr[32][33], Ti[32][33];
    int bid = blockIdx.x;
    int arr = bid >> 10;
    int tix = bid & 1023;
    int ctTile = tix >> 3, mTile = tix & 7;
    const float* Sr = arr ? w1r : w0r;
    const float* Si = arr ? w1i : w0i;
    int tx = threadIdx.x & 31, ty = threadIdx.x >> 5;
    #pragma unroll
    for (int yy = 0; yy < 4; yy++) {
        int r = ty + yy * 8;
        int row = ctTile * 32 + r, col = mTile * 32 + tx;
        Tr[r][tx] = Sr[row * 256 + col];
        Ti[r][tx] = Si[row * 256 + col];
    }
    __syncthreads();
    #pragma unroll
    for (int yy = 0; yy < 4; yy++) {
        int r = ty + yy * 8;
        int m = arr * 256 + mTile * 32 + r;
        int ct = ctTile * 32 + tx;
        g_W[(size_t)m * 4096 + ct] = make_float2(Tr[tx][r], Ti[tx][r]);
    }
}

// ---------------------------------------------------------------------------
// K1: forward. grid = 1024 blocks, 128 threads, Xs2/Fw smem overlay.
// ---------------------------------------------------------------------------
__global__ void __launch_bounds__(128, 8) k_forward(const float* __restrict__ X) {
    __shared__ __align__(16) ull TWB[128][2];   // (c,-s),(s,c) — 2KB
    __shared__ __align__(16) char u_smem[17408];  // Xs2 / Fw overlay
    float2 (*Xs2)[17] = (float2(*)[17])u_smem;
    ull    (*Fw)[129] = (ull(*)[129])u_smem;

    int tid = threadIdx.x;
    {
        float s, c; sincosf(PI2_OVER_128 * (float)tid, &s, &c);
        TWB[tid][0] = pk2(c, -s);
        TWB[tid][1] = pk2(s, c);
    }

    const float* Xp = X + (size_t)blockIdx.x * 16384;

    float ar[16], ai[16];
    #pragma unroll
    for (int k = 0; k < 16; k++) { ar[k] = 0.f; ai[k] = 0.f; }

    #pragma unroll 1
    for (int c0 = 0; c0 < 64; c0 += 16) {
        __syncthreads();
        #pragma unroll
        for (int p = 0; p < 8; p++) {
            int i = p * 128 + tid;
            int r = i >> 3, q = i & 7;
            const float* src = (q < 4) ? (Xp + r * 128 + c0 + q * 4)
                                       : (Xp + r * 128 + c0 + 64 + (q - 4) * 4);
            float4 v = *(const float4*)src;
            if (q < 4) {
                Xs2[r][q * 4 + 0].x = v.x; Xs2[r][q * 4 + 1].x = v.y;
                Xs2[r][q * 4 + 2].x = v.z; Xs2[r][q * 4 + 3].x = v.w;
            } else {
                Xs2[r][(q - 4) * 4 + 0].y = v.x; Xs2[r][(q - 4) * 4 + 1].y = v.y;
                Xs2[r][(q - 4) * 4 + 2].y = v.z; Xs2[r][(q - 4) * 4 + 3].y = v.w;
            }
        }
        __syncthreads();
        switch (c0) {
            case 0:  chunkA<0 >(Xs2, tid, ar, ai); break;
            case 16: chunkA<16>(Xs2, tid, ar, ai); break;
            case 32: chunkA<32>(Xs2, tid, ar, ai); break;
            default: chunkA<48>(Xs2, tid, ar, ai); break;
        }
    }

    __syncthreads();
    #pragma unroll
    for (int k = 0; k < 16; k++) Fw[k][tid] = pk2(ar[k], ai[k]);
    __syncthreads();

    int ky = tid & 15, kxg = tid >> 4;
    ull accB[4] = {0, 0, 0, 0}, accC[4] = {0, 0, 0, 0};
    int kxv[4], idx[4];
    #pragma unroll
    for (int j = 0; j < 4; j++) {
        int kxIdx = kxg * 4 + j;
        kxv[j] = (kxIdx < 16) ? kxIdx : (96 + kxIdx);
        idx[j] = 0;
    }
    for (int h = 0; h < 64; h++) {
        ull a = Fw[ky][h], b = Fw[ky][h + 64];
        ull p = add2(a, b), m = sub2(a, b);
        float pr, pi, mr, mi;
        upk2(p, pr, pi); upk2(m, mr, mi);
        ull prr = pk2(pr, pr), pii = pk2(pi, pi);
        ull mrr = pk2(mr, mr), mii = pk2(mi, mi);
        #pragma unroll
        for (int j = 0; j < 4; j++) {
            ulonglong2 e = *(const ulonglong2*)&TWB[idx[j]][0];
            if (j & 1) { fma2(accB[j], mrr, e.x); fma2(accC[j], mii, e.y); }
            else       { fma2(accB[j], prr, e.x); fma2(accC[j], pii, e.y); }
            idx[j] = (idx[j] + kxv[j]) & 127;
        }
    }
    int b = blockIdx.x >> 6, t = blockIdx.x & 63;
    #pragma unroll
    for (int j = 0; j < 4; j++) {
        int m = (kxg * 4 + j) * 16 + ky;
        ull r = add2(accB[j], accC[j]);
        float re, im; upk2(r, re, im);
        g_Xf[m * 1024 + t * 16 + b] = make_float2(re, im);
    }
}

// ---------------------------------------------------------------------------
// K2: mode mixing. grid = 512, 256 threads. b in lanes -> weights broadcast.
// ---------------------------------------------------------------------------
__global__ void __launch_bounds__(256) k_modes() {
    extern __shared__ __align__(16) char sm2[];
    ulonglong2* Wsp = (ulonglong2*)sm2;                          // [64 t][65]
    ulonglong2* Xsm = (ulonglong2*)(sm2 + 64 * 65 * 16);         // [64 t][16 b]
    ull*        Ys2 = (ull*)(sm2 + 64 * 65 * 16 + 64 * 16 * 16); // [1024]

    int m = blockIdx.x, tid = threadIdx.x;

    #pragma unroll
    for (int p = 0; p < 16; p++) {
        int i = tid + p * 256;
        float2 w = g_W[(size_t)m * 4096 + i];
        Wsp[(i & 63) * 65 + (i >> 6)] = make_ulonglong2(pk2(w.x, w.x), pk2(w.y, w.y));
    }
    #pragma unroll
    for (int p = 0; p < 4; p++) {
        int i = tid + p * 256;
        float2 x = g_Xf[m * 1024 + i];
        Xsm[i] = make_ulonglong2(pk2(x.x, x.y), pk2(-x.y, x.x));
    }
    __syncthreads();

    int b = tid & 15, cq = tid >> 4;
    ull acc[4] = {0, 0, 0, 0};
    for (int t = 0; t < 64; t++) {
        ulonglong2 xv = Xsm[t * 16 + b];
        #pragma unroll
        for (int j = 0; j < 4; j++) {
            ulonglong2 wv = Wsp[t * 65 + cq * 4 + j];
            fma2(acc[j], wv.x, xv.x);
            fma2(acc[j], wv.y, xv.y);
        }
    }
    #pragma unroll
    for (int j = 0; j < 4; j++) Ys2[b * 64 + cq * 4 + j] = acc[j];
    __syncthreads();
    #pragma unroll
    for (int p = 0; p < 4; p++) {
        int i = tid + p * 256;
        *(ull*)&g_Y[(size_t)m * 1024 + i] = Ys2[i];
    }
}

// ---------------------------------------------------------------------------
// K3: inverse. grid = 1024 blocks, 256 threads, <=64 regs -> 4 blocks/SM.
// Radix-2 fold in kx parity (phase A) and ky parity (phase B).
// Phase B: 2 w-values x 4 rows per thread.
// ---------------------------------------------------------------------------
__global__ void __launch_bounds__(256, 4) k_inverse(float* __restrict__ out) {
    __shared__ __align__(16) ull TWI[128][2];       // (c,s),(-s,c) — 2KB
    __shared__ __align__(16) ulonglong2 TWIB[128];  // ((2c,2c),(-2s,-2s)) — 2KB
    __shared__ ull Ysm[512];                        // 4KB
    __shared__ __align__(16) ulonglong2 ZZ[64][17]; // [(zr_h,zr_h64),(zi_h,zi_h64)]

    int tid = threadIdx.x;
    if (tid < 128) {
        float s, c; sincosf(PI2_OVER_128 * (float)tid, &s, &c);
        TWI[tid][0] = pk2(c, s);
        TWI[tid][1] = pk2(-s, c);
        TWIB[tid] = make_ulonglong2(pk2(2.f * c, 2.f * c), pk2(-2.f * s, -2.f * s));
    }
    int off = blockIdx.x;   // b*64 + c
    Ysm[tid]       = *(const ull*)&g_Y[(size_t)tid * 1024 + off];
    Ysm[tid + 256] = *(const ull*)&g_Y[(size_t)(tid + 256) * 1024 + off];
    __syncthreads();

    // Phase A: Z[h] = Se+So, Z[h+64] = Se-So. Thread: h in {hq,hq+16,hq+32,hq+48}.
    {
        int ky = tid & 15, hq = tid >> 4;          // hq in 0..15
        ull Se[4] = {0, 0, 0, 0}, So[4] = {0, 0, 0, 0};
        int idx[4] = {0, 0, 0, 0};

        #pragma unroll
        for (int kxI = 0; kxI < 16; kxI++) {       // kx = kxI
            float yr, yi; upk2(Ysm[kxI * 16 + ky], yr, yi);
            ull yrr = pk2(yr, yr), yii = pk2(yi, yi);
            #pragma unroll
            for (int u = 0; u < 4; u++) {
                ulonglong2 e = *(const ulonglong2*)&TWI[idx[u]][0];
                if (kxI & 1) { fma2(So[u], yrr, e.x); fma2(So[u], yii, e.y); }
                else         { fma2(Se[u], yrr, e.x); fma2(Se[u], yii, e.y); }
                idx[u] = (idx[u] + hq + 16 * u) & 127;
            }
        }
        #pragma unroll
        for (int u = 0; u < 4; u++) idx[u] = (112 * (hq + 16 * u)) & 127;
        #pragma unroll
        for (int kxI = 16; kxI < 32; kxI++) {      // kx = 96+kxI, same parity
            float yr, yi; upk2(Ysm[kxI * 16 + ky], yr, yi);
            ull yrr = pk2(yr, yr), yii = pk2(yi, yi);
            #pragma unroll
            for (int u = 0; u < 4; u++) {
                ulonglong2 e = *(const ulonglong2*)&TWI[idx[u]][0];
                if (kxI & 1) { fma2(So[u], yrr, e.x); fma2(So[u], yii, e.y); }
                else         { fma2(Se[u], yrr, e.x); fma2(Se[u], yii, e.y); }
                idx[u] = (idx[u] + hq + 16 * u) & 127;
            }
        }
        #pragma unroll
        for (int u = 0; u < 4; u++) {
            int r = hq + 16 * u;
            ull zp = add2(Se[u], So[u]);   // h = r
            ull zm = sub2(Se[u], So[u]);   // h = r + 64
            float pr, pi, mr, mi;
            upk2(zp, pr, pi); upk2(zm, mr, mi);
            ZZ[r][ky] = make_ulonglong2(pk2(pr, mr), pk2(pi, mi));
        }
    }
    __syncthreads();

    // Phase B: thread (wl, rg) handles w in {wl, wl+32} (each +64 via parity)
    // for 4 rows per pass, 2 passes. 16 ull accumulators.
    int wl = tid & 31, rg = tid >> 5;      // rg in 0..7
    float* op = out + (size_t)blockIdx.x * 16384;
    #pragma unroll 1
    for (int pass = 0; pass < 2; pass++) {
        int r0 = rg * 4 + pass * 32;
        ull E1[4], O1[4], E2[4], O2[4];
        #pragma unroll
        for (int i = 0; i < 4; i++) {
            ull z0 = ZZ[r0 + i][0].x;      // ky=0: Re(Z0), weight 1
            E1[i] = z0; O1[i] = 0;
            E2[i] = z0; O2[i] = 0;
        }
        int a1 = wl, a2 = wl + 32;
        #pragma unroll
        for (int k = 1; k < 16; k++) {
            ulonglong2 e1 = TWIB[a1];
            ulonglong2 e2 = TWIB[a2];
            if (k & 1) {
                #pragma unroll
                for (int i = 0; i < 4; i++) {
                    ulonglong2 zz = ZZ[r0 + i][k];
                    fma2(O1[i], zz.x, e1.x); fma2(O1[i], zz.y, e1.y);
                    fma2(O2[i], zz.x, e2.x); fma2(O2[i], zz.y, e2.y);
                }
            } else {
                #pragma unroll
                for (int i = 0; i < 4; i++) {
                    ulonglong2 zz = ZZ[r0 + i][k];
                    fma2(E1[i], zz.x, e1.x); fma2(E1[i], zz.y, e1.y);
                    fma2(E2[i], zz.x, e2.x); fma2(E2[i], zz.y, e2.y);
                }
            }
            a1 = (a1 + wl) & 127;
            a2 = (a2 + wl + 32) & 127;
        }
        #pragma unroll
        for (int i = 0; i < 4; i++) {
            int r = r0 + i;
            ull oa = add2(E1[i], O1[i]);   // w = wl
            ull ob = sub2(E1[i], O1[i]);   // w = wl + 64
            ull oc = add2(E2[i], O2[i]);   // w = wl + 32
            ull od = sub2(E2[i], O2[i]);   // w = wl + 96
            float a0, a64, b0, b64, c0, c64, d0, d64;
            upk2(oa, a0, a64); upk2(ob, b0, b64);
            upk2(oc, c0, c64); upk2(od, d0, d64);
            op[r * 128 + wl]             = a0;
            op[(r + 64) * 128 + wl]      = a64;
            op[r * 128 + wl + 64]        = b0;
            op[(r + 64) * 128 + wl + 64] = b64;
            op[r * 128 + wl + 32]        = c0;
            op[(r + 64) * 128 + wl + 32] = c64;
            op[r * 128 + wl + 96]        = d0;
            op[(r + 64) * 128 + wl + 96] = d64;
        }
    }
}

// ---------------------------------------------------------------------------
extern "C" void kernel_launch(void* const* d_in, const int* in_sizes, int n_in,
                              void* d_out, int out_size) {
    const float* X   = (const float*)d_in[0];
    const float* w0r = (const float*)d_in[1];
    const float* w0i = (const float*)d_in[2];
    const float* w1r = (const float*)d_in[3];
    const float* w1i = (const float*)d_in[4];
    float* out = (float*)d_out;

    static bool attr_done = false;
    if (!attr_done) {
        cudaFuncSetAttribute(k_modes, cudaFuncAttributeMaxDynamicSharedMemorySize,
                             91136);
        attr_done = true;
    }

    k_transpose<<<2048, 256>>>(w0r, w0i, w1r, w1i);
    k_forward<<<1024, 128>>>(X);
    k_modes<<<512, 256, 91136>>>();
    k_inverse<<<1024, 256>>>(out);
}

// round 12
// speedup vs baseline: 1.4589x; 1.4259x over previous
#include <cuda_runtime.h>
#include <cstdint>

// FactorizedSpectralConv on GB300 — radix-2 folded direct DFTs (R8 restore).
// R12: exact R8 pipeline; k_inverse phase B uses precomputed TWIB table.
// B=16, C=64, H=W=128, M0=M1=16.

typedef unsigned long long ull;
#define PI2_OVER_128 0.04908738521234051935f  // 2*pi/128
#define SGN2 0x8000000080000000ULL

// Scratch (device globals; allocation-free rule)
__device__ float2 g_Xf[512 * 1024];   // [m][t*16+b], 4 MB
__device__ float2 g_Y [512 * 1024];   // [m][b*64+c], 4 MB
__device__ float2 g_W [512 * 4096];   // [m][c*64+t], 16 MB (transposed weights)

__device__ __forceinline__ ull pk2(float x, float y) {
    ull r; asm("mov.b64 %0,{%1,%2};" : "=l"(r) : "f"(x), "f"(y)); return r;
}
__device__ __forceinline__ void upk2(ull v, float& x, float& y) {
    asm("mov.b64 {%0,%1},%2;" : "=f"(x), "=f"(y) : "l"(v));
}
__device__ __forceinline__ void fma2(ull& d, ull a, ull b) {
    asm("fma.rn.f32x2 %0,%1,%2,%0;" : "+l"(d) : "l"(a), "l"(b));
}
__device__ __forceinline__ ull add2(ull a, ull b) {
    ull d; asm("add.rn.f32x2 %0,%1,%2;" : "=l"(d) : "l"(a), "l"(b)); return d;
}
__device__ __forceinline__ ull sub2(ull a, ull b) {
    return add2(a, b ^ SGN2);
}

// ---- compile-time trig (double Taylor, |x| <= pi, err ~1e-11) ----
constexpr double PI_D = 3.14159265358979323846264338327950288;
__host__ __device__ constexpr double tsin_(double x) {
    double t = x, s = x, x2 = x * x;
    for (int i = 1; i <= 12; i++) { t *= -x2 / double((2 * i) * (2 * i + 1)); s += t; }
    return s;
}
__host__ __device__ constexpr double tcos_(double x) {
    double t = 1.0, s = 1.0, x2 = x * x;
    for (int i = 1; i <= 12; i++) { t *= -x2 / double((2 * i - 1) * (2 * i)); s += t; }
    return s;
}
__host__ __device__ constexpr float TWC(int w, int k) {   // cos/16384
    int n = (w * k) & 127;
    double x = (2.0 * PI_D * n) / 128.0;
    if (n > 64) x -= 2.0 * PI_D;
    return (float)(tcos_(x) / 16384.0);
}
__host__ __device__ constexpr float TWS(int w, int k) {   // -sin/16384
    int n = (w * k) & 127;
    double x = (2.0 * PI_D * n) / 128.0;
    if (n > 64) x -= 2.0 * PI_D;
    return (float)(-tsin_(x) / 16384.0);
}

// ---- templated phase-A MAC ladder: all twiddles become FFMA immediates ----
template <int W, int K = 0>
__device__ __forceinline__ void rowA(float xp, float xm, float* ar, float* ai) {
    if constexpr (K < 16) {
        constexpr float c = TWC(W, K);
        constexpr float s = TWS(W, K);
        float x = (K & 1) ? xm : xp;
        ar[K] = fmaf(x, c, ar[K]);
        ai[K] = fmaf(x, s, ai[K]);
        rowA<W, K + 1>(xp, xm, ar, ai);
    }
}
template <int C0, int W2 = 0>
__device__ __forceinline__ void chunkA(const float2 (*Xs2)[17], int tid,
                                       float* ar, float* ai) {
    if constexpr (W2 < 16) {
        float2 xv = Xs2[tid][W2];
        rowA<C0 + W2>(xv.x + xv.y, xv.x - xv.y, ar, ai);
        chunkA<C0, W2 + 1>(Xs2, tid, ar, ai);
    }
}

// ---------------------------------------------------------------------------
// K0: weight transpose  w[c][t][kx0][ky] (stride-256 cols) -> g_W[m][c*64+t]
// ---------------------------------------------------------------------------
__global__ void __launch_bounds__(256) k_transpose(
    const float* __restrict__ w0r, const float* __restrict__ w0i,
    const float* __restrict__ w1r, const float* __restrict__ w1i) {
    __shared__ float Tr[32][33], Ti[32][33];
    int bid = blockIdx.x;
    int arr = bid >> 10;
    int tix = bid & 1023;
    int ctTile = tix >> 3, mTile = tix & 7;
    const float* Sr = arr ? w1r : w0r;
    const float* Si = arr ? w1i : w0i;
    int tx = threadIdx.x & 31, ty = threadIdx.x >> 5;
    #pragma unroll
    for (int yy = 0; yy < 4; yy++) {
        int r = ty + yy * 8;
        int row = ctTile * 32 + r, col = mTile * 32 + tx;
        Tr[r][tx] = Sr[row * 256 + col];
        Ti[r][tx] = Si[row * 256 + col];
    }
    __syncthreads();
    #pragma unroll
    for (int yy = 0; yy < 4; yy++) {
        int r = ty + yy * 8;
        int m = arr * 256 + mTile * 32 + r;
        int ct = ctTile * 32 + tx;
        g_W[(size_t)m * 4096 + ct] = make_float2(Tr[tx][r], Ti[tx][r]);
    }
}

// ---------------------------------------------------------------------------
// K1: forward. grid = 1024 blocks, 128 threads, Xs2/Fw smem overlay.
// ---------------------------------------------------------------------------
__global__ void __launch_bounds__(128, 8) k_forward(const float* __restrict__ X) {
    __shared__ __align__(16) ull TWB[128][2];   // (c,-s),(s,c) — 2KB
    __shared__ __align__(16) char u_smem[17408];  // Xs2 / Fw overlay
    float2 (*Xs2)[17] = (float2(*)[17])u_smem;
    ull    (*Fw)[129] = (ull(*)[129])u_smem;

    int tid = threadIdx.x;
    {
        float s, c; sincosf(PI2_OVER_128 * (float)tid, &s, &c);
        TWB[tid][0] = pk2(c, -s);
        TWB[tid][1] = pk2(s, c);
    }

    const float* Xp = X + (size_t)blockIdx.x * 16384;

    float ar[16], ai[16];
    #pragma unroll
    for (int k = 0; k < 16; k++) { ar[k] = 0.f; ai[k] = 0.f; }

    #pragma unroll 1
    for (int c0 = 0; c0 < 64; c0 += 16) {
        __syncthreads();
        #pragma unroll
        for (int p = 0; p < 8; p++) {
            int i = p * 128 + tid;
            int r = i >> 3, q = i & 7;
            const float* src = (q < 4) ? (Xp + r * 128 + c0 + q * 4)
                                       : (Xp + r * 128 + c0 + 64 + (q - 4) * 4);
            float4 v = *(const float4*)src;
            if (q < 4) {
                Xs2[r][q * 4 + 0].x = v.x; Xs2[r][q * 4 + 1].x = v.y;
                Xs2[r][q * 4 + 2].x = v.z; Xs2[r][q * 4 + 3].x = v.w;
            } else {
                Xs2[r][(q - 4) * 4 + 0].y = v.x; Xs2[r][(q - 4) * 4 + 1].y = v.y;
                Xs2[r][(q - 4) * 4 + 2].y = v.z; Xs2[r][(q - 4) * 4 + 3].y = v.w;
            }
        }
        __syncthreads();
        switch (c0) {
            case 0:  chunkA<0 >(Xs2, tid, ar, ai); break;
            case 16: chunkA<16>(Xs2, tid, ar, ai); break;
            case 32: chunkA<32>(Xs2, tid, ar, ai); break;
            default: chunkA<48>(Xs2, tid, ar, ai); break;
        }
    }

    __syncthreads();
    #pragma unroll
    for (int k = 0; k < 16; k++) Fw[k][tid] = pk2(ar[k], ai[k]);
    __syncthreads();

    int ky = tid & 15, kxg = tid >> 4;
    ull accB[4] = {0, 0, 0, 0}, accC[4] = {0, 0, 0, 0};
    int kxv[4], idx[4];
    #pragma unroll
    for (int j = 0; j < 4; j++) {
        int kxIdx = kxg * 4 + j;
        kxv[j] = (kxIdx < 16) ? kxIdx : (96 + kxIdx);
        idx[j] = 0;
    }
    for (int h = 0; h < 64; h++) {
        ull a = Fw[ky][h], b = Fw[ky][h + 64];
        ull p = add2(a, b), m = sub2(a, b);
        float pr, pi, mr, mi;
        upk2(p, pr, pi); upk2(m, mr, mi);
        ull prr = pk2(pr, pr), pii = pk2(pi, pi);
        ull mrr = pk2(mr, mr), mii = pk2(mi, mi);
        #pragma unroll
        for (int j = 0; j < 4; j++) {
            ulonglong2 e = *(const ulonglong2*)&TWB[idx[j]][0];
            if (j & 1) { fma2(accB[j], mrr, e.x); fma2(accC[j], mii, e.y); }
            else       { fma2(accB[j], prr, e.x); fma2(accC[j], pii, e.y); }
            idx[j] = (idx[j] + kxv[j]) & 127;
        }
    }
    int b = blockIdx.x >> 6, t = blockIdx.x & 63;
    #pragma unroll
    for (int j = 0; j < 4; j++) {
        int m = (kxg * 4 + j) * 16 + ky;
        ull r = add2(accB[j], accC[j]);
        float re, im; upk2(r, re, im);
        g_Xf[m * 1024 + t * 16 + b] = make_float2(re, im);
    }
}

// ---------------------------------------------------------------------------
// K2: mode mixing. grid = 512, 256 threads. b in lanes -> weights broadcast.
// ---------------------------------------------------------------------------
__global__ void __launch_bounds__(256) k_modes() {
    extern __shared__ __align__(16) char sm2[];
    ulonglong2* Wsp = (ulonglong2*)sm2;                          // [64 t][65]
    ulonglong2* Xsm = (ulonglong2*)(sm2 + 64 * 65 * 16);         // [64 t][16 b]
    ull*        Ys2 = (ull*)(sm2 + 64 * 65 * 16 + 64 * 16 * 16); // [1024]

    int m = blockIdx.x, tid = threadIdx.x;

    #pragma unroll
    for (int p = 0; p < 16; p++) {
        int i = tid + p * 256;
        float2 w = g_W[(size_t)m * 4096 + i];
        Wsp[(i & 63) * 65 + (i >> 6)] = make_ulonglong2(pk2(w.x, w.x), pk2(w.y, w.y));
    }
    #pragma unroll
    for (int p = 0; p < 4; p++) {
        int i = tid + p * 256;
        float2 x = g_Xf[m * 1024 + i];
        Xsm[i] = make_ulonglong2(pk2(x.x, x.y), pk2(-x.y, x.x));
    }
    __syncthreads();

    int b = tid & 15, cq = tid >> 4;
    ull acc[4] = {0, 0, 0, 0};
    for (int t = 0; t < 64; t++) {
        ulonglong2 xv = Xsm[t * 16 + b];
        #pragma unroll
        for (int j = 0; j < 4; j++) {
            ulonglong2 wv = Wsp[t * 65 + cq * 4 + j];
            fma2(acc[j], wv.x, xv.x);
            fma2(acc[j], wv.y, xv.y);
        }
    }
    #pragma unroll
    for (int j = 0; j < 4; j++) Ys2[b * 64 + cq * 4 + j] = acc[j];
    __syncthreads();
    #pragma unroll
    for (int p = 0; p < 4; p++) {
        int i = tid + p * 256;
        *(ull*)&g_Y[(size_t)m * 1024 + i] = Ys2[i];
    }
}

// ---------------------------------------------------------------------------
// K3: inverse. grid = 1024 blocks, 256 threads, <=64 regs -> 4 blocks/SM.
// Radix-2 fold in kx parity (phase A) and ky parity (phase B).
// Phase B shape identical to R8 (1 w-column x 8 rows); TWIB table replaces
// per-k twiddle recompute.
// ---------------------------------------------------------------------------
__global__ void __launch_bounds__(256, 4) k_inverse(float* __restrict__ out) {
    __shared__ __align__(16) ull TWI[128][2];       // (c,s),(-s,c) — 2KB
    __shared__ __align__(16) ulonglong2 TWIB[128];  // ((2c,2c),(-2s,-2s)) — 2KB
    __shared__ ull Ysm[512];                        // 4KB
    __shared__ __align__(16) ulonglong2 ZZ[64][17]; // [(zr_h,zr_h64),(zi_h,zi_h64)]

    int tid = threadIdx.x;
    if (tid < 128) {
        float s, c; sincosf(PI2_OVER_128 * (float)tid, &s, &c);
        TWI[tid][0] = pk2(c, s);
        TWI[tid][1] = pk2(-s, c);
        TWIB[tid] = make_ulonglong2(pk2(2.f * c, 2.f * c), pk2(-2.f * s, -2.f * s));
    }
    int off = blockIdx.x;   // b*64 + c
    Ysm[tid]       = *(const ull*)&g_Y[(size_t)tid * 1024 + off];
    Ysm[tid + 256] = *(const ull*)&g_Y[(size_t)(tid + 256) * 1024 + off];
    __syncthreads();

    // Phase A: Z[h] = Se+So, Z[h+64] = Se-So. Thread: h in {hq,hq+16,hq+32,hq+48}.
    {
        int ky = tid & 15, hq = tid >> 4;          // hq in 0..15
        ull Se[4] = {0, 0, 0, 0}, So[4] = {0, 0, 0, 0};
        int idx[4] = {0, 0, 0, 0};

        #pragma unroll
        for (int kxI = 0; kxI < 16; kxI++) {       // kx = kxI
            float yr, yi; upk2(Ysm[kxI * 16 + ky], yr, yi);
            ull yrr = pk2(yr, yr), yii = pk2(yi, yi);
            #pragma unroll
            for (int u = 0; u < 4; u++) {
                ulonglong2 e = *(const ulonglong2*)&TWI[idx[u]][0];
                if (kxI & 1) { fma2(So[u], yrr, e.x); fma2(So[u], yii, e.y); }
                else         { fma2(Se[u], yrr, e.x); fma2(Se[u], yii, e.y); }
                idx[u] = (idx[u] + hq + 16 * u) & 127;
            }
        }
        #pragma unroll
        for (int u = 0; u < 4; u++) idx[u] = (112 * (hq + 16 * u)) & 127;
        #pragma unroll
        for (int kxI = 16; kxI < 32; kxI++) {      // kx = 96+kxI, same parity
            float yr, yi; upk2(Ysm[kxI * 16 + ky], yr, yi);
            ull yrr = pk2(yr, yr), yii = pk2(yi, yi);
            #pragma unroll
            for (int u = 0; u < 4; u++) {
                ulonglong2 e = *(const ulonglong2*)&TWI[idx[u]][0];
                if (kxI & 1) { fma2(So[u], yrr, e.x); fma2(So[u], yii, e.y); }
                else         { fma2(Se[u], yrr, e.x); fma2(Se[u], yii, e.y); }
                idx[u] = (idx[u] + hq + 16 * u) & 127;
            }
        }
        #pragma unroll
        for (int u = 0; u < 4; u++) {
            int r = hq + 16 * u;
            ull zp = add2(Se[u], So[u]);   // h = r
            ull zm = sub2(Se[u], So[u]);   // h = r + 64
            float pr, pi, mr, mi;
            upk2(zp, pr, pi); upk2(zm, mr, mi);
            ZZ[r][ky] = make_ulonglong2(pk2(pr, mr), pk2(pi, mi));
        }
    }
    __syncthreads();

    // Phase B: out[r,wl] = accE+accO, out[r,wl+64] = accE-accO (ky parity fold).
    // Two passes of 8 rows -> 16 ull accumulators, fits 64-reg budget. (R8 shape)
    int wl = tid & 63, rg = tid >> 6;      // rg in 0..3
    float* op = out + (size_t)blockIdx.x * 16384;
    #pragma unroll 1
    for (int pass = 0; pass < 2; pass++) {
        int r0 = rg * 16 + pass * 8;
        ull accE[8], accO[8];
        #pragma unroll
        for (int i = 0; i < 8; i++) {
            accE[i] = ZZ[r0 + i][0].x;     // ky=0: Re(Z0), weight 1
            accO[i] = 0;
        }
        #pragma unroll
        for (int k = 1; k < 16; k++) {
            ulonglong2 e = TWIB[(k * wl) & 127];
            if (k & 1) {
                #pragma unroll
                for (int i = 0; i < 8; i++) {
                    ulonglong2 zz = ZZ[r0 + i][k];
                    fma2(accO[i], zz.x, e.x);
                    fma2(accO[i], zz.y, e.y);
                }
            } else {
                #pragma unroll
                for (int i = 0; i < 8; i++) {
                    ulonglong2 zz = ZZ[r0 + i][k];
                    fma2(accE[i], zz.x, e.x);
                    fma2(accE[i], zz.y, e.y);
                }
            }
        }
        #pragma unroll
        for (int i = 0; i < 8; i++) {
            int r = r0 + i;
            ull olo = add2(accE[i], accO[i]);   // w = wl
            ull ohi = sub2(accE[i], accO[i]);   // w = wl + 64
            float a0, a1, b0, b1;
            upk2(olo, a0, a1);                  // (h=r, h=r+64)
            upk2(ohi, b0, b1);
            op[r * 128 + wl]             = a0;
            op[(r + 64) * 128 + wl]      = a1;
            op[r * 128 + wl + 64]        = b0;
            op[(r + 64) * 128 + wl + 64] = b1;
        }
    }
}

// ---------------------------------------------------------------------------
extern "C" void kernel_launch(void* const* d_in, const int* in_sizes, int n_in,
                              void* d_out, int out_size) {
    const float* X   = (const float*)d_in[0];
    const float* w0r = (const float*)d_in[1];
    const float* w0i = (const float*)d_in[2];
    const float* w1r = (const float*)d_in[3];
    const float* w1i = (const float*)d_in[4];
    float* out = (float*)d_out;

    static bool attr_done = false;
    if (!attr_done) {
        cudaFuncSetAttribute(k_modes, cudaFuncAttributeMaxDynamicSharedMemorySize,
                             91136);
        attr_done = true;
    }

    k_transpose<<<2048, 256>>>(w0r, w0i, w1r, w1i);
    k_forward<<<1024, 128>>>(X);
    k_modes<<<512, 256, 91136>>>();
    k_inverse<<<1024, 256>>>(out);
}

// round 13
// speedup vs baseline: 1.4997x; 1.0280x over previous
#include <cuda_runtime.h>
#include <cstdint>

// FactorizedSpectralConv on GB300 — radix-2 folded direct DFTs (R8 exact core).
// R13: k_transpose/g_W eliminated; k_modes loads weights directly from the
// original stride-256 layout (L2-shared across m-blocks). Hot loops untouched.
// B=16, C=64, H=W=128, M0=M1=16.

typedef unsigned long long ull;
#define PI2_OVER_128 0.04908738521234051935f  // 2*pi/128
#define SGN2 0x8000000080000000ULL

// Scratch (device globals; allocation-free rule)
__device__ float2 g_Xf[512 * 1024];   // [m][t*16+b], 4 MB
__device__ float2 g_Y [512 * 1024];   // [m][b*64+c], 4 MB

__device__ __forceinline__ ull pk2(float x, float y) {
    ull r; asm("mov.b64 %0,{%1,%2};" : "=l"(r) : "f"(x), "f"(y)); return r;
}
__device__ __forceinline__ void upk2(ull v, float& x, float& y) {
    asm("mov.b64 {%0,%1},%2;" : "=f"(x), "=f"(y) : "l"(v));
}
__device__ __forceinline__ void fma2(ull& d, ull a, ull b) {
    asm("fma.rn.f32x2 %0,%1,%2,%0;" : "+l"(d) : "l"(a), "l"(b));
}
__device__ __forceinline__ ull add2(ull a, ull b) {
    ull d; asm("add.rn.f32x2 %0,%1,%2;" : "=l"(d) : "l"(a), "l"(b)); return d;
}
__device__ __forceinline__ ull sub2(ull a, ull b) {
    return add2(a, b ^ SGN2);
}

// ---- compile-time trig (double Taylor, |x| <= pi, err ~1e-11) ----
constexpr double PI_D = 3.14159265358979323846264338327950288;
__host__ __device__ constexpr double tsin_(double x) {
    double t = x, s = x, x2 = x * x;
    for (int i = 1; i <= 12; i++) { t *= -x2 / double((2 * i) * (2 * i + 1)); s += t; }
    return s;
}
__host__ __device__ constexpr double tcos_(double x) {
    double t = 1.0, s = 1.0, x2 = x * x;
    for (int i = 1; i <= 12; i++) { t *= -x2 / double((2 * i - 1) * (2 * i)); s += t; }
    return s;
}
__host__ __device__ constexpr float TWC(int w, int k) {   // cos/16384
    int n = (w * k) & 127;
    double x = (2.0 * PI_D * n) / 128.0;
    if (n > 64) x -= 2.0 * PI_D;
    return (float)(tcos_(x) / 16384.0);
}
__host__ __device__ constexpr float TWS(int w, int k) {   // -sin/16384
    int n = (w * k) & 127;
    double x = (2.0 * PI_D * n) / 128.0;
    if (n > 64) x -= 2.0 * PI_D;
    return (float)(-tsin_(x) / 16384.0);
}

// ---- templated phase-A MAC ladder: all twiddles become FFMA immediates ----
template <int W, int K = 0>
__device__ __forceinline__ void rowA(float xp, float xm, float* ar, float* ai) {
    if constexpr (K < 16) {
        constexpr float c = TWC(W, K);
        constexpr float s = TWS(W, K);
        float x = (K & 1) ? xm : xp;
        ar[K] = fmaf(x, c, ar[K]);
        ai[K] = fmaf(x, s, ai[K]);
        rowA<W, K + 1>(xp, xm, ar, ai);
    }
}
template <int C0, int W2 = 0>
__device__ __forceinline__ void chunkA(const float2 (*Xs2)[17], int tid,
                                       float* ar, float* ai) {
    if constexpr (W2 < 16) {
        float2 xv = Xs2[tid][W2];
        rowA<C0 + W2>(xv.x + xv.y, xv.x - xv.y, ar, ai);
        chunkA<C0, W2 + 1>(Xs2, tid, ar, ai);
    }
}

// ---------------------------------------------------------------------------
// K1: forward. grid = 1024 blocks, 128 threads, Xs2/Fw smem overlay.
// ---------------------------------------------------------------------------
__global__ void __launch_bounds__(128, 8) k_forward(const float* __restrict__ X) {
    __shared__ __align__(16) ull TWB[128][2];   // (c,-s),(s,c) — 2KB
    __shared__ __align__(16) char u_smem[17408];  // Xs2 / Fw overlay
    float2 (*Xs2)[17] = (float2(*)[17])u_smem;
    ull    (*Fw)[129] = (ull(*)[129])u_smem;

    int tid = threadIdx.x;
    {
        float s, c; sincosf(PI2_OVER_128 * (float)tid, &s, &c);
        TWB[tid][0] = pk2(c, -s);
        TWB[tid][1] = pk2(s, c);
    }

    const float* Xp = X + (size_t)blockIdx.x * 16384;

    float ar[16], ai[16];
    #pragma unroll
    for (int k = 0; k < 16; k++) { ar[k] = 0.f; ai[k] = 0.f; }

    #pragma unroll 1
    for (int c0 = 0; c0 < 64; c0 += 16) {
        __syncthreads();
        #pragma unroll
        for (int p = 0; p < 8; p++) {
            int i = p * 128 + tid;
            int r = i >> 3, q = i & 7;
            const float* src = (q < 4) ? (Xp + r * 128 + c0 + q * 4)
                                       : (Xp + r * 128 + c0 + 64 + (q - 4) * 4);
            float4 v = *(const float4*)src;
            if (q < 4) {
                Xs2[r][q * 4 + 0].x = v.x; Xs2[r][q * 4 + 1].x = v.y;
                Xs2[r][q * 4 + 2].x = v.z; Xs2[r][q * 4 + 3].x = v.w;
            } else {
                Xs2[r][(q - 4) * 4 + 0].y = v.x; Xs2[r][(q - 4) * 4 + 1].y = v.y;
                Xs2[r][(q - 4) * 4 + 2].y = v.z; Xs2[r][(q - 4) * 4 + 3].y = v.w;
            }
        }
        __syncthreads();
        switch (c0) {
            case 0:  chunkA<0 >(Xs2, tid, ar, ai); break;
            case 16: chunkA<16>(Xs2, tid, ar, ai); break;
            case 32: chunkA<32>(Xs2, tid, ar, ai); break;
            default: chunkA<48>(Xs2, tid, ar, ai); break;
        }
    }

    __syncthreads();
    #pragma unroll
    for (int k = 0; k < 16; k++) Fw[k][tid] = pk2(ar[k], ai[k]);
    __syncthreads();

    int ky = tid & 15, kxg = tid >> 4;
    ull accB[4] = {0, 0, 0, 0}, accC[4] = {0, 0, 0, 0};
    int kxv[4], idx[4];
    #pragma unroll
    for (int j = 0; j < 4; j++) {
        int kxIdx = kxg * 4 + j;
        kxv[j] = (kxIdx < 16) ? kxIdx : (96 + kxIdx);
        idx[j] = 0;
    }
    for (int h = 0; h < 64; h++) {
        ull a = Fw[ky][h], b = Fw[ky][h + 64];
        ull p = add2(a, b), m = sub2(a, b);
        float pr, pi, mr, mi;
        upk2(p, pr, pi); upk2(m, mr, mi);
        ull prr = pk2(pr, pr), pii = pk2(pi, pi);
        ull mrr = pk2(mr, mr), mii = pk2(mi, mi);
        #pragma unroll
        for (int j = 0; j < 4; j++) {
            ulonglong2 e = *(const ulonglong2*)&TWB[idx[j]][0];
            if (j & 1) { fma2(accB[j], mrr, e.x); fma2(accC[j], mii, e.y); }
            else       { fma2(accB[j], prr, e.x); fma2(accC[j], pii, e.y); }
            idx[j] = (idx[j] + kxv[j]) & 127;
        }
    }
    int b = blockIdx.x >> 6, t = blockIdx.x & 63;
    #pragma unroll
    for (int j = 0; j < 4; j++) {
        int m = (kxg * 4 + j) * 16 + ky;
        ull r = add2(accB[j], accC[j]);
        float re, im; upk2(r, re, im);
        g_Xf[m * 1024 + t * 16 + b] = make_float2(re, im);
    }
}

// ---------------------------------------------------------------------------
// K2: mode mixing. grid = 512, 256 threads. Weights loaded directly from the
// original [c][t][kx0][ky] layout (stride-256 scatter; L2-shared across m).
// b in lanes -> weights broadcast in the GEMM loop (unchanged from R8).
// ---------------------------------------------------------------------------
__global__ void __launch_bounds__(256) k_modes(
    const float* __restrict__ w0r, const float* __restrict__ w0i,
    const float* __restrict__ w1r, const float* __restrict__ w1i) {
    extern __shared__ __align__(16) char sm2[];
    ulonglong2* Wsp = (ulonglong2*)sm2;                          // [64 t][65]
    ulonglong2* Xsm = (ulonglong2*)(sm2 + 64 * 65 * 16);         // [64 t][16 b]
    ull*        Ys2 = (ull*)(sm2 + 64 * 65 * 16 + 64 * 16 * 16); // [1024]

    int m = blockIdx.x, tid = threadIdx.x;
    int kxIdx = m >> 4, ky = m & 15;
    const float* Wr = (kxIdx < 16) ? w0r : w1r;
    const float* Wi = (kxIdx < 16) ? w0i : w1i;
    int kx0 = (kxIdx < 16) ? kxIdx : (kxIdx - 16);
    int woff = kx0 * 16 + ky;

    #pragma unroll
    for (int p = 0; p < 16; p++) {
        int i = tid + p * 256;                 // i = c*64 + t
        float wr = Wr[i * 256 + woff];
        float wi = Wi[i * 256 + woff];
        Wsp[(i & 63) * 65 + (i >> 6)] = make_ulonglong2(pk2(wr, wr), pk2(wi, wi));
    }
    #pragma unroll
    for (int p = 0; p < 4; p++) {
        int i = tid + p * 256;
        float2 x = g_Xf[m * 1024 + i];
        Xsm[i] = make_ulonglong2(pk2(x.x, x.y), pk2(-x.y, x.x));
    }
    __syncthreads();

    int b = tid & 15, cq = tid >> 4;
    ull acc[4] = {0, 0, 0, 0};
    for (int t = 0; t < 64; t++) {
        ulonglong2 xv = Xsm[t * 16 + b];
        #pragma unroll
        for (int j = 0; j < 4; j++) {
            ulonglong2 wv = Wsp[t * 65 + cq * 4 + j];
            fma2(acc[j], wv.x, xv.x);
            fma2(acc[j], wv.y, xv.y);
        }
    }
    #pragma unroll
    for (int j = 0; j < 4; j++) Ys2[b * 64 + cq * 4 + j] = acc[j];
    __syncthreads();
    #pragma unroll
    for (int p = 0; p < 4; p++) {
        int i = tid + p * 256;
        *(ull*)&g_Y[(size_t)m * 1024 + i] = Ys2[i];
    }
}

// ---------------------------------------------------------------------------
// K3: inverse. grid = 1024 blocks, 256 threads, <=64 regs -> 4 blocks/SM.
// EXACT R8 kernel (the proven 35.2us configuration).
// ---------------------------------------------------------------------------
__global__ void __launch_bounds__(256, 4) k_inverse(float* __restrict__ out) {
    __shared__ __align__(16) ull TWI[128][2];       // (c,s),(-s,c) — 2KB
    __shared__ ull Ysm[512];                        // 4KB
    __shared__ __align__(16) ulonglong2 ZZ[64][17]; // [(zr_h,zr_h64),(zi_h,zi_h64)]

    int tid = threadIdx.x;
    if (tid < 128) {
        float s, c; sincosf(PI2_OVER_128 * (float)tid, &s, &c);
        TWI[tid][0] = pk2(c, s);
        TWI[tid][1] = pk2(-s, c);
    }
    int off = blockIdx.x;   // b*64 + c
    Ysm[tid]       = *(const ull*)&g_Y[(size_t)tid * 1024 + off];
    Ysm[tid + 256] = *(const ull*)&g_Y[(size_t)(tid + 256) * 1024 + off];
    __syncthreads();

    // Phase A: Z[h] = Se+So, Z[h+64] = Se-So. Thread: h in {hq,hq+16,hq+32,hq+48}.
    {
        int ky = tid & 15, hq = tid >> 4;          // hq in 0..15
        ull Se[4] = {0, 0, 0, 0}, So[4] = {0, 0, 0, 0};
        int idx[4] = {0, 0, 0, 0};

        #pragma unroll
        for (int kxI = 0; kxI < 16; kxI++) {       // kx = kxI
            float yr, yi; upk2(Ysm[kxI * 16 + ky], yr, yi);
            ull yrr = pk2(yr, yr), yii = pk2(yi, yi);
            #pragma unroll
            for (int u = 0; u < 4; u++) {
                ulonglong2 e = *(const ulonglong2*)&TWI[idx[u]][0];
                if (kxI & 1) { fma2(So[u], yrr, e.x); fma2(So[u], yii, e.y); }
                else         { fma2(Se[u], yrr, e.x); fma2(Se[u], yii, e.y); }
                idx[u] = (idx[u] + hq + 16 * u) & 127;
            }
        }
        #pragma unroll
        for (int u = 0; u < 4; u++) idx[u] = (112 * (hq + 16 * u)) & 127;
        #pragma unroll
        for (int kxI = 16; kxI < 32; kxI++) {      // kx = 96+kxI, same parity
            float yr, yi; upk2(Ysm[kxI * 16 + ky], yr, yi);
            ull yrr = pk2(yr, yr), yii = pk2(yi, yi);
            #pragma unroll
            for (int u = 0; u < 4; u++) {
                ulonglong2 e = *(const ulonglong2*)&TWI[idx[u]][0];
                if (kxI & 1) { fma2(So[u], yrr, e.x); fma2(So[u], yii, e.y); }
                else         { fma2(Se[u], yrr, e.x); fma2(Se[u], yii, e.y); }
                idx[u] = (idx[u] + hq + 16 * u) & 127;
            }
        }
        #pragma unroll
        for (int u = 0; u < 4; u++) {
            int r = hq + 16 * u;
            ull zp = add2(Se[u], So[u]);   // h = r
            ull zm = sub2(Se[u], So[u]);   // h = r + 64
            float pr, pi, mr, mi;
            upk2(zp, pr, pi); upk2(zm, mr, mi);
            ZZ[r][ky] = make_ulonglong2(pk2(pr, mr), pk2(pi, mi));
        }
    }
    __syncthreads();

    // Phase B: out[r,wl] = accE+accO, out[r,wl+64] = accE-accO (ky parity fold).
    // Two passes of 8 rows -> 16 ull accumulators, fits 64-reg budget.
    int wl = tid & 63, rg = tid >> 6;      // rg in 0..3
    float* op = out + (size_t)blockIdx.x * 16384;
    #pragma unroll 1
    for (int pass = 0; pass < 2; pass++) {
        int r0 = rg * 16 + pass * 8;
        ull accE[8], accO[8];
        #pragma unroll
        for (int i = 0; i < 8; i++) {
            accE[i] = ZZ[r0 + i][0].x;     // ky=0: Re(Z0), weight 1
            accO[i] = 0;
        }
        #pragma unroll
        for (int k = 1; k < 16; k++) {
            float c, s; upk2(TWI[(k * wl) & 127][0], c, s);
            ull tcp = pk2(2.f * c, 2.f * c);
            ull tsp = pk2(-2.f * s, -2.f * s);
            if (k & 1) {
                #pragma unroll
                for (int i = 0; i < 8; i++) {
                    ulonglong2 zz = ZZ[r0 + i][k];
                    fma2(accO[i], zz.x, tcp);
                    fma2(accO[i], zz.y, tsp);
                }
            } else {
                #pragma unroll
                for (int i = 0; i < 8; i++) {
                    ulonglong2 zz = ZZ[r0 + i][k];
                    fma2(accE[i], zz.x, tcp);
                    fma2(accE[i], zz.y, tsp);
                }
            }
        }
        #pragma unroll
        for (int i = 0; i < 8; i++) {
            int r = r0 + i;
            ull olo = add2(accE[i], accO[i]);   // w = wl
            ull ohi = sub2(accE[i], accO[i]);   // w = wl + 64
            float a0, a1, b0, b1;
            upk2(olo, a0, a1);                  // (h=r, h=r+64)
            upk2(ohi, b0, b1);
            op[r * 128 + wl]             = a0;
            op[(r + 64) * 128 + wl]      = a1;
            op[r * 128 + wl + 64]        = b0;
            op[(r + 64) * 128 + wl + 64] = b1;
        }
    }
}

// ---------------------------------------------------------------------------
extern "C" void kernel_launch(void* const* d_in, const int* in_sizes, int n_in,
                              void* d_out, int out_size) {
    const float* X   = (const float*)d_in[0];
    const float* w0r = (const float*)d_in[1];
    const float* w0i = (const float*)d_in[2];
    const float* w1r = (const float*)d_in[3];
    const float* w1i = (const float*)d_in[4];
    float* out = (float*)d_out;

    static bool attr_done = false;
    if (!attr_done) {
        cudaFuncSetAttribute(k_modes, cudaFuncAttributeMaxDynamicSharedMemorySize,
                             91136);
        attr_done = true;
    }

    k_forward<<<1024, 128>>>(X);
    k_modes<<<512, 256, 91136>>>(w0r, w0i, w1r, w1i);
    k_inverse<<<1024, 256>>>(out);
}

// round 14
// speedup vs baseline: 1.8100x; 1.2069x over previous
#include <cuda_runtime.h>
#include <cstdint>

// FactorizedSpectralConv on GB300 — radix-2 folded direct DFTs (R8 base).
// R14: exact R8 pipeline (k_transpose/g_W restored); single change =
// radix-4 h-fold in k_forward phase B (kx mod 4 == j per thread slot).
// B=16, C=64, H=W=128, M0=M1=16.

typedef unsigned long long ull;
#define PI2_OVER_128 0.04908738521234051935f  // 2*pi/128
#define SGN2 0x8000000080000000ULL

// Scratch (device globals; allocation-free rule)
__device__ float2 g_Xf[512 * 1024];   // [m][t*16+b], 4 MB
__device__ float2 g_Y [512 * 1024];   // [m][b*64+c], 4 MB
__device__ float2 g_W [512 * 4096];   // [m][c*64+t], 16 MB (transposed weights)

__device__ __forceinline__ ull pk2(float x, float y) {
    ull r; asm("mov.b64 %0,{%1,%2};" : "=l"(r) : "f"(x), "f"(y)); return r;
}
__device__ __forceinline__ void upk2(ull v, float& x, float& y) {
    asm("mov.b64 {%0,%1},%2;" : "=f"(x), "=f"(y) : "l"(v));
}
__device__ __forceinline__ void fma2(ull& d, ull a, ull b) {
    asm("fma.rn.f32x2 %0,%1,%2,%0;" : "+l"(d) : "l"(a), "l"(b));
}
__device__ __forceinline__ ull add2(ull a, ull b) {
    ull d; asm("add.rn.f32x2 %0,%1,%2;" : "=l"(d) : "l"(a), "l"(b)); return d;
}
__device__ __forceinline__ ull sub2(ull a, ull b) {
    return add2(a, b ^ SGN2);
}

// ---- compile-time trig (double Taylor, |x| <= pi, err ~1e-11) ----
constexpr double PI_D = 3.14159265358979323846264338327950288;
__host__ __device__ constexpr double tsin_(double x) {
    double t = x, s = x, x2 = x * x;
    for (int i = 1; i <= 12; i++) { t *= -x2 / double((2 * i) * (2 * i + 1)); s += t; }
    return s;
}
__host__ __device__ constexpr double tcos_(double x) {
    double t = 1.0, s = 1.0, x2 = x * x;
    for (int i = 1; i <= 12; i++) { t *= -x2 / double((2 * i - 1) * (2 * i)); s += t; }
    return s;
}
__host__ __device__ constexpr float TWC(int w, int k) {   // cos/16384
    int n = (w * k) & 127;
    double x = (2.0 * PI_D * n) / 128.0;
    if (n > 64) x -= 2.0 * PI_D;
    return (float)(tcos_(x) / 16384.0);
}
__host__ __device__ constexpr float TWS(int w, int k) {   // -sin/16384
    int n = (w * k) & 127;
    double x = (2.0 * PI_D * n) / 128.0;
    if (n > 64) x -= 2.0 * PI_D;
    return (float)(-tsin_(x) / 16384.0);
}

// ---- templated phase-A MAC ladder: all twiddles become FFMA immediates ----
template <int W, int K = 0>
__device__ __forceinline__ void rowA(float xp, float xm, float* ar, float* ai) {
    if constexpr (K < 16) {
        constexpr float c = TWC(W, K);
        constexpr float s = TWS(W, K);
        float x = (K & 1) ? xm : xp;
        ar[K] = fmaf(x, c, ar[K]);
        ai[K] = fmaf(x, s, ai[K]);
        rowA<W, K + 1>(xp, xm, ar, ai);
    }
}
template <int C0, int W2 = 0>
__device__ __forceinline__ void chunkA(const float2 (*Xs2)[17], int tid,
                                       float* ar, float* ai) {
    if constexpr (W2 < 16) {
        float2 xv = Xs2[tid][W2];
        rowA<C0 + W2>(xv.x + xv.y, xv.x - xv.y, ar, ai);
        chunkA<C0, W2 + 1>(Xs2, tid, ar, ai);
    }
}

// ---------------------------------------------------------------------------
// K0: weight transpose  w[c][t][kx0][ky] (stride-256 cols) -> g_W[m][c*64+t]
// ---------------------------------------------------------------------------
__global__ void __launch_bounds__(256) k_transpose(
    const float* __restrict__ w0r, const float* __restrict__ w0i,
    const float* __restrict__ w1r, const float* __restrict__ w1i) {
    __shared__ float Tr[32][33], Ti[32][33];
    int bid = blockIdx.x;
    int arr = bid >> 10;
    int tix = bid & 1023;
    int ctTile = tix >> 3, mTile = tix & 7;
    const float* Sr = arr ? w1r : w0r;
    const float* Si = arr ? w1i : w0i;
    int tx = threadIdx.x & 31, ty = threadIdx.x >> 5;
    #pragma unroll
    for (int yy = 0; yy < 4; yy++) {
        int r = ty + yy * 8;
        int row = ctTile * 32 + r, col = mTile * 32 + tx;
        Tr[r][tx] = Sr[row * 256 + col];
        Ti[r][tx] = Si[row * 256 + col];
    }
    __syncthreads();
    #pragma unroll
    for (int yy = 0; yy < 4; yy++) {
        int r = ty + yy * 8;
        int m = arr * 256 + mTile * 32 + r;
        int ct = ctTile * 32 + tx;
        g_W[(size_t)m * 4096 + ct] = make_float2(Tr[tx][r], Ti[tx][r]);
    }
}

// ---------------------------------------------------------------------------
// K1: forward. grid = 1024 blocks, 128 threads, Xs2/Fw smem overlay.
// Phase A: immediate-twiddle FFMA. Phase B: radix-4 h-fold.
// ---------------------------------------------------------------------------
__global__ void __launch_bounds__(128, 8) k_forward(const float* __restrict__ X) {
    __shared__ __align__(16) ull TWB[128][2];   // (c,-s),(s,c) — 2KB
    __shared__ __align__(16) char u_smem[17408];  // Xs2 / Fw overlay
    float2 (*Xs2)[17] = (float2(*)[17])u_smem;
    ull    (*Fw)[129] = (ull(*)[129])u_smem;

    int tid = threadIdx.x;
    {
        float s, c; sincosf(PI2_OVER_128 * (float)tid, &s, &c);
        TWB[tid][0] = pk2(c, -s);
        TWB[tid][1] = pk2(s, c);
    }

    const float* Xp = X + (size_t)blockIdx.x * 16384;

    float ar[16], ai[16];
    #pragma unroll
    for (int k = 0; k < 16; k++) { ar[k] = 0.f; ai[k] = 0.f; }

    #pragma unroll 1
    for (int c0 = 0; c0 < 64; c0 += 16) {
        __syncthreads();
        #pragma unroll
        for (int p = 0; p < 8; p++) {
            int i = p * 128 + tid;
            int r = i >> 3, q = i & 7;
            const float* src = (q < 4) ? (Xp + r * 128 + c0 + q * 4)
                                       : (Xp + r * 128 + c0 + 64 + (q - 4) * 4);
            float4 v = *(const float4*)src;
            if (q < 4) {
                Xs2[r][q * 4 + 0].x = v.x; Xs2[r][q * 4 + 1].x = v.y;
                Xs2[r][q * 4 + 2].x = v.z; Xs2[r][q * 4 + 3].x = v.w;
            } else {
                Xs2[r][(q - 4) * 4 + 0].y = v.x; Xs2[r][(q - 4) * 4 + 1].y = v.y;
                Xs2[r][(q - 4) * 4 + 2].y = v.z; Xs2[r][(q - 4) * 4 + 3].y = v.w;
            }
        }
        __syncthreads();
        switch (c0) {
            case 0:  chunkA<0 >(Xs2, tid, ar, ai); break;
            case 16: chunkA<16>(Xs2, tid, ar, ai); break;
            case 32: chunkA<32>(Xs2, tid, ar, ai); break;
            default: chunkA<48>(Xs2, tid, ar, ai); break;
        }
    }

    __syncthreads();
    #pragma unroll
    for (int k = 0; k < 16; k++) Fw[k][tid] = pk2(ar[k], ai[k]);
    __syncthreads();

    // Phase B (radix-4): Xf[kx] = sum_{h<32} G_j[h] E(kx h), kx mod 4 == j.
    // G0 = (F0+F2)+(F1+F3), G2 = (F0+F2)-(F1+F3),
    // G1 = B - iD, G3 = B + iD with B=F0-F2, D=F1-F3, iD=(-Di, Dr).
    int ky = tid & 15, kxg = tid >> 4;
    ull accB[4] = {0, 0, 0, 0}, accC[4] = {0, 0, 0, 0};
    int kxv[4], idx[4];
    #pragma unroll
    for (int j = 0; j < 4; j++) {
        int kxIdx = kxg * 4 + j;
        kxv[j] = (kxIdx < 16) ? kxIdx : (96 + kxIdx);  // kxv mod 4 == j
        idx[j] = 0;
    }
    for (int h = 0; h < 32; h++) {
        ull F0 = Fw[ky][h],      F1 = Fw[ky][h + 32];
        ull F2 = Fw[ky][h + 64], F3 = Fw[ky][h + 96];
        ull A  = add2(F0, F2), Bv = sub2(F0, F2);
        ull Cv = add2(F1, F3), Dv = sub2(F1, F3);
        ull G0 = add2(A, Cv),  G2 = sub2(A, Cv);
        float g0r, g0i, g2r, g2i, br, bi, dr, di;
        upk2(G0, g0r, g0i); upk2(G2, g2r, g2i);
        upk2(Bv, br, bi);   upk2(Dv, dr, di);
        float grs[4], gis[4];
        grs[0] = g0r;      gis[0] = g0i;
        grs[1] = br + di;  gis[1] = bi - dr;   // G1 = B - iD
        grs[2] = g2r;      gis[2] = g2i;
        grs[3] = br - di;  gis[3] = bi + dr;   // G3 = B + iD
        #pragma unroll
        for (int j = 0; j < 4; j++) {
            ulonglong2 e = *(const ulonglong2*)&TWB[idx[j]][0];
            fma2(accB[j], pk2(grs[j], grs[j]), e.x);
            fma2(accC[j], pk2(gis[j], gis[j]), e.y);
            idx[j] = (idx[j] + kxv[j]) & 127;
        }
    }
    int b = blockIdx.x >> 6, t = blockIdx.x & 63;
    #pragma unroll
    for (int j = 0; j < 4; j++) {
        int m = (kxg * 4 + j) * 16 + ky;
        ull r = add2(accB[j], accC[j]);
        float re, im; upk2(r, re, im);
        g_Xf[m * 1024 + t * 16 + b] = make_float2(re, im);
    }
}

// ---------------------------------------------------------------------------
// K2: mode mixing. grid = 512, 256 threads. b in lanes -> weights broadcast.
// (exact R8)
// ---------------------------------------------------------------------------
__global__ void __launch_bounds__(256) k_modes() {
    extern __shared__ __align__(16) char sm2[];
    ulonglong2* Wsp = (ulonglong2*)sm2;                          // [64 t][65]
    ulonglong2* Xsm = (ulonglong2*)(sm2 + 64 * 65 * 16);         // [64 t][16 b]
    ull*        Ys2 = (ull*)(sm2 + 64 * 65 * 16 + 64 * 16 * 16); // [1024]

    int m = blockIdx.x, tid = threadIdx.x;

    #pragma unroll
    for (int p = 0; p < 16; p++) {
        int i = tid + p * 256;
        float2 w = g_W[(size_t)m * 4096 + i];
        Wsp[(i & 63) * 65 + (i >> 6)] = make_ulonglong2(pk2(w.x, w.x), pk2(w.y, w.y));
    }
    #pragma unroll
    for (int p = 0; p < 4; p++) {
        int i = tid + p * 256;
        float2 x = g_Xf[m * 1024 + i];
        Xsm[i] = make_ulonglong2(pk2(x.x, x.y), pk2(-x.y, x.x));
    }
    __syncthreads();

    int b = tid & 15, cq = tid >> 4;
    ull acc[4] = {0, 0, 0, 0};
    for (int t = 0; t < 64; t++) {
        ulonglong2 xv = Xsm[t * 16 + b];
        #pragma unroll
        for (int j = 0; j < 4; j++) {
            ulonglong2 wv = Wsp[t * 65 + cq * 4 + j];
            fma2(acc[j], wv.x, xv.x);
            fma2(acc[j], wv.y, xv.y);
        }
    }
    #pragma unroll
    for (int j = 0; j < 4; j++) Ys2[b * 64 + cq * 4 + j] = acc[j];
    __syncthreads();
    #pragma unroll
    for (int p = 0; p < 4; p++) {
        int i = tid + p * 256;
        *(ull*)&g_Y[(size_t)m * 1024 + i] = Ys2[i];
    }
}

// ---------------------------------------------------------------------------
// K3: inverse. grid = 1024 blocks, 256 threads, <=64 regs -> 4 blocks/SM.
// EXACT R8 kernel (proven 35.2us). Do not touch.
// ---------------------------------------------------------------------------
__global__ void __launch_bounds__(256, 4) k_inverse(float* __restrict__ out) {
    __shared__ __align__(16) ull TWI[128][2];       // (c,s),(-s,c) — 2KB
    __shared__ ull Ysm[512];                        // 4KB
    __shared__ __align__(16) ulonglong2 ZZ[64][17]; // [(zr_h,zr_h64),(zi_h,zi_h64)]

    int tid = threadIdx.x;
    if (tid < 128) {
        float s, c; sincosf(PI2_OVER_128 * (float)tid, &s, &c);
        TWI[tid][0] = pk2(c, s);
        TWI[tid][1] = pk2(-s, c);
    }
    int off = blockIdx.x;   // b*64 + c
    Ysm[tid]       = *(const ull*)&g_Y[(size_t)tid * 1024 + off];
    Ysm[tid + 256] = *(const ull*)&g_Y[(size_t)(tid + 256) * 1024 + off];
    __syncthreads();

    // Phase A: Z[h] = Se+So, Z[h+64] = Se-So. Thread: h in {hq,hq+16,hq+32,hq+48}.
    {
        int ky = tid & 15, hq = tid >> 4;          // hq in 0..15
        ull Se[4] = {0, 0, 0, 0}, So[4] = {0, 0, 0, 0};
        int idx[4] = {0, 0, 0, 0};

        #pragma unroll
        for (int kxI = 0; kxI < 16; kxI++) {       // kx = kxI
            float yr, yi; upk2(Ysm[kxI * 16 + ky], yr, yi);
            ull yrr = pk2(yr, yr), yii = pk2(yi, yi);
            #pragma unroll
            for (int u = 0; u < 4; u++) {
                ulonglong2 e = *(const ulonglong2*)&TWI[idx[u]][0];
                if (kxI & 1) { fma2(So[u], yrr, e.x); fma2(So[u], yii, e.y); }
                else         { fma2(Se[u], yrr, e.x); fma2(Se[u], yii, e.y); }
                idx[u] = (idx[u] + hq + 16 * u) & 127;
            }
        }
        #pragma unroll
        for (int u = 0; u < 4; u++) idx[u] = (112 * (hq + 16 * u)) & 127;
        #pragma unroll
        for (int kxI = 16; kxI < 32; kxI++) {      // kx = 96+kxI, same parity
            float yr, yi; upk2(Ysm[kxI * 16 + ky], yr, yi);
            ull yrr = pk2(yr, yr), yii = pk2(yi, yi);
            #pragma unroll
            for (int u = 0; u < 4; u++) {
                ulonglong2 e = *(const ulonglong2*)&TWI[idx[u]][0];
                if (kxI & 1) { fma2(So[u], yrr, e.x); fma2(So[u], yii, e.y); }
                else         { fma2(Se[u], yrr, e.x); fma2(Se[u], yii, e.y); }
                idx[u] = (idx[u] + hq + 16 * u) & 127;
            }
        }
        #pragma unroll
        for (int u = 0; u < 4; u++) {
            int r = hq + 16 * u;
            ull zp = add2(Se[u], So[u]);   // h = r
            ull zm = sub2(Se[u], So[u]);   // h = r + 64
            float pr, pi, mr, mi;
            upk2(zp, pr, pi); upk2(zm, mr, mi);
            ZZ[r][ky] = make_ulonglong2(pk2(pr, mr), pk2(pi, mi));
        }
    }
    __syncthreads();

    // Phase B: out[r,wl] = accE+accO, out[r,wl+64] = accE-accO (ky parity fold).
    int wl = tid & 63, rg = tid >> 6;      // rg in 0..3
    float* op = out + (size_t)blockIdx.x * 16384;
    #pragma unroll 1
    for (int pass = 0; pass < 2; pass++) {
        int r0 = rg * 16 + pass * 8;
        ull accE[8], accO[8];
        #pragma unroll
        for (int i = 0; i < 8; i++) {
            accE[i] = ZZ[r0 + i][0].x;     // ky=0: Re(Z0), weight 1
            accO[i] = 0;
        }
        #pragma unroll
        for (int k = 1; k < 16; k++) {
            float c, s; upk2(TWI[(k * wl) & 127][0], c, s);
            ull tcp = pk2(2.f * c, 2.f * c);
            ull tsp = pk2(-2.f * s, -2.f * s);
            if (k & 1) {
                #pragma unroll
                for (int i = 0; i < 8; i++) {
                    ulonglong2 zz = ZZ[r0 + i][k];
                    fma2(accO[i], zz.x, tcp);
                    fma2(accO[i], zz.y, tsp);
                }
            } else {
                #pragma unroll
                for (int i = 0; i < 8; i++) {
                    ulonglong2 zz = ZZ[r0 + i][k];
                    fma2(accE[i], zz.x, tcp);
                    fma2(accE[i], zz.y, tsp);
                }
            }
        }
        #pragma unroll
        for (int i = 0; i < 8; i++) {
            int r = r0 + i;
            ull olo = add2(accE[i], accO[i]);   // w = wl
            ull ohi = sub2(accE[i], accO[i]);   // w = wl + 64
            float a0, a1, b0, b1;
            upk2(olo, a0, a1);                  // (h=r, h=r+64)
            upk2(ohi, b0, b1);
            op[r * 128 + wl]             = a0;
            op[(r + 64) * 128 + wl]      = a1;
            op[r * 128 + wl + 64]        = b0;
            op[(r + 64) * 128 + wl + 64] = b1;
        }
    }
}

// ---------------------------------------------------------------------------
extern "C" void kernel_launch(void* const* d_in, const int* in_sizes, int n_in,
                              void* d_out, int out_size) {
    const float* X   = (const float*)d_in[0];
    const float* w0r = (const float*)d_in[1];
    const float* w0i = (const float*)d_in[2];
    const float* w1r = (const float*)d_in[3];
    const float* w1i = (const float*)d_in[4];
    float* out = (float*)d_out;

    static bool attr_done = false;
    if (!attr_done) {
        cudaFuncSetAttribute(k_modes, cudaFuncAttributeMaxDynamicSharedMemorySize,
                             91136);
        attr_done = true;
    }

    k_transpose<<<2048, 256>>>(w0r, w0i, w1r, w1i);
    k_forward<<<1024, 128>>>(X);
    k_modes<<<512, 256, 91136>>>();
    k_inverse<<<1024, 256>>>(out);
}

// round 15
// speedup vs baseline: 1.8494x; 1.0218x over previous
#include <cuda_runtime.h>
#include <cstdint>

// FactorizedSpectralConv on GB300 — radix-4 folded direct DFTs.
// R15 = R14 + radix-4 kx-fold in k_inverse phase A (mirror of R14's win).
// B=16, C=64, H=W=128, M0=M1=16.

typedef unsigned long long ull;
#define PI2_OVER_128 0.04908738521234051935f  // 2*pi/128
#define SGN2 0x8000000080000000ULL

// Scratch (device globals; allocation-free rule)
__device__ float2 g_Xf[512 * 1024];   // [m][t*16+b], 4 MB
__device__ float2 g_Y [512 * 1024];   // [m][b*64+c], 4 MB
__device__ float2 g_W [512 * 4096];   // [m][c*64+t], 16 MB (transposed weights)

__device__ __forceinline__ ull pk2(float x, float y) {
    ull r; asm("mov.b64 %0,{%1,%2};" : "=l"(r) : "f"(x), "f"(y)); return r;
}
__device__ __forceinline__ void upk2(ull v, float& x, float& y) {
    asm("mov.b64 {%0,%1},%2;" : "=f"(x), "=f"(y) : "l"(v));
}
__device__ __forceinline__ void fma2(ull& d, ull a, ull b) {
    asm("fma.rn.f32x2 %0,%1,%2,%0;" : "+l"(d) : "l"(a), "l"(b));
}
__device__ __forceinline__ ull add2(ull a, ull b) {
    ull d; asm("add.rn.f32x2 %0,%1,%2;" : "=l"(d) : "l"(a), "l"(b)); return d;
}
__device__ __forceinline__ ull sub2(ull a, ull b) {
    return add2(a, b ^ SGN2);
}

// ---- compile-time trig (double Taylor, |x| <= pi, err ~1e-11) ----
constexpr double PI_D = 3.14159265358979323846264338327950288;
__host__ __device__ constexpr double tsin_(double x) {
    double t = x, s = x, x2 = x * x;
    for (int i = 1; i <= 12; i++) { t *= -x2 / double((2 * i) * (2 * i + 1)); s += t; }
    return s;
}
__host__ __device__ constexpr double tcos_(double x) {
    double t = 1.0, s = 1.0, x2 = x * x;
    for (int i = 1; i <= 12; i++) { t *= -x2 / double((2 * i - 1) * (2 * i)); s += t; }
    return s;
}
__host__ __device__ constexpr float TWC(int w, int k) {   // cos/16384
    int n = (w * k) & 127;
    double x = (2.0 * PI_D * n) / 128.0;
    if (n > 64) x -= 2.0 * PI_D;
    return (float)(tcos_(x) / 16384.0);
}
__host__ __device__ constexpr float TWS(int w, int k) {   // -sin/16384
    int n = (w * k) & 127;
    double x = (2.0 * PI_D * n) / 128.0;
    if (n > 64) x -= 2.0 * PI_D;
    return (float)(-tsin_(x) / 16384.0);
}

// ---- templated phase-A MAC ladder: all twiddles become FFMA immediates ----
template <int W, int K = 0>
__device__ __forceinline__ void rowA(float xp, float xm, float* ar, float* ai) {
    if constexpr (K < 16) {
        constexpr float c = TWC(W, K);
        constexpr float s = TWS(W, K);
        float x = (K & 1) ? xm : xp;
        ar[K] = fmaf(x, c, ar[K]);
        ai[K] = fmaf(x, s, ai[K]);
        rowA<W, K + 1>(xp, xm, ar, ai);
    }
}
template <int C0, int W2 = 0>
__device__ __forceinline__ void chunkA(const float2 (*Xs2)[17], int tid,
                                       float* ar, float* ai) {
    if constexpr (W2 < 16) {
        float2 xv = Xs2[tid][W2];
        rowA<C0 + W2>(xv.x + xv.y, xv.x - xv.y, ar, ai);
        chunkA<C0, W2 + 1>(Xs2, tid, ar, ai);
    }
}

// ---------------------------------------------------------------------------
// K0: weight transpose  w[c][t][kx0][ky] (stride-256 cols) -> g_W[m][c*64+t]
// ---------------------------------------------------------------------------
__global__ void __launch_bounds__(256) k_transpose(
    const float* __restrict__ w0r, const float* __restrict__ w0i,
    const float* __restrict__ w1r, const float* __restrict__ w1i) {
    __shared__ float Tr[32][33], Ti[32][33];
    int bid = blockIdx.x;
    int arr = bid >> 10;
    int tix = bid & 1023;
    int ctTile = tix >> 3, mTile = tix & 7;
    const float* Sr = arr ? w1r : w0r;
    const float* Si = arr ? w1i : w0i;
    int tx = threadIdx.x & 31, ty = threadIdx.x >> 5;
    #pragma unroll
    for (int yy = 0; yy < 4; yy++) {
        int r = ty + yy * 8;
        int row = ctTile * 32 + r, col = mTile * 32 + tx;
        Tr[r][tx] = Sr[row * 256 + col];
        Ti[r][tx] = Si[row * 256 + col];
    }
    __syncthreads();
    #pragma unroll
    for (int yy = 0; yy < 4; yy++) {
        int r = ty + yy * 8;
        int m = arr * 256 + mTile * 32 + r;
        int ct = ctTile * 32 + tx;
        g_W[(size_t)m * 4096 + ct] = make_float2(Tr[tx][r], Ti[tx][r]);
    }
}

// ---------------------------------------------------------------------------
// K1: forward. grid = 1024 blocks, 128 threads, Xs2/Fw smem overlay.
// Phase A: immediate-twiddle FFMA. Phase B: radix-4 h-fold. (exact R14)
// ---------------------------------------------------------------------------
__global__ void __launch_bounds__(128, 8) k_forward(const float* __restrict__ X) {
    __shared__ __align__(16) ull TWB[128][2];   // (c,-s),(s,c) — 2KB
    __shared__ __align__(16) char u_smem[17408];  // Xs2 / Fw overlay
    float2 (*Xs2)[17] = (float2(*)[17])u_smem;
    ull    (*Fw)[129] = (ull(*)[129])u_smem;

    int tid = threadIdx.x;
    {
        float s, c; sincosf(PI2_OVER_128 * (float)tid, &s, &c);
        TWB[tid][0] = pk2(c, -s);
        TWB[tid][1] = pk2(s, c);
    }

    const float* Xp = X + (size_t)blockIdx.x * 16384;

    float ar[16], ai[16];
    #pragma unroll
    for (int k = 0; k < 16; k++) { ar[k] = 0.f; ai[k] = 0.f; }

    #pragma unroll 1
    for (int c0 = 0; c0 < 64; c0 += 16) {
        __syncthreads();
        #pragma unroll
        for (int p = 0; p < 8; p++) {
            int i = p * 128 + tid;
            int r = i >> 3, q = i & 7;
            const float* src = (q < 4) ? (Xp + r * 128 + c0 + q * 4)
                                       : (Xp + r * 128 + c0 + 64 + (q - 4) * 4);
            float4 v = *(const float4*)src;
            if (q < 4) {
                Xs2[r][q * 4 + 0].x = v.x; Xs2[r][q * 4 + 1].x = v.y;
                Xs2[r][q * 4 + 2].x = v.z; Xs2[r][q * 4 + 3].x = v.w;
            } else {
                Xs2[r][(q - 4) * 4 + 0].y = v.x; Xs2[r][(q - 4) * 4 + 1].y = v.y;
                Xs2[r][(q - 4) * 4 + 2].y = v.z; Xs2[r][(q - 4) * 4 + 3].y = v.w;
            }
        }
        __syncthreads();
        switch (c0) {
            case 0:  chunkA<0 >(Xs2, tid, ar, ai); break;
            case 16: chunkA<16>(Xs2, tid, ar, ai); break;
            case 32: chunkA<32>(Xs2, tid, ar, ai); break;
            default: chunkA<48>(Xs2, tid, ar, ai); break;
        }
    }

    __syncthreads();
    #pragma unroll
    for (int k = 0; k < 16; k++) Fw[k][tid] = pk2(ar[k], ai[k]);
    __syncthreads();

    // Phase B (radix-4): Xf[kx] = sum_{h<32} G_j[h] E(kx h), kx mod 4 == j.
    int ky = tid & 15, kxg = tid >> 4;
    ull accB[4] = {0, 0, 0, 0}, accC[4] = {0, 0, 0, 0};
    int kxv[4], idx[4];
    #pragma unroll
    for (int j = 0; j < 4; j++) {
        int kxIdx = kxg * 4 + j;
        kxv[j] = (kxIdx < 16) ? kxIdx : (96 + kxIdx);  // kxv mod 4 == j
        idx[j] = 0;
    }
    for (int h = 0; h < 32; h++) {
        ull F0 = Fw[ky][h],      F1 = Fw[ky][h + 32];
        ull F2 = Fw[ky][h + 64], F3 = Fw[ky][h + 96];
        ull A  = add2(F0, F2), Bv = sub2(F0, F2);
        ull Cv = add2(F1, F3), Dv = sub2(F1, F3);
        ull G0 = add2(A, Cv),  G2 = sub2(A, Cv);
        float g0r, g0i, g2r, g2i, br, bi, dr, di;
        upk2(G0, g0r, g0i); upk2(G2, g2r, g2i);
        upk2(Bv, br, bi);   upk2(Dv, dr, di);
        float grs[4], gis[4];
        grs[0] = g0r;      gis[0] = g0i;
        grs[1] = br + di;  gis[1] = bi - dr;   // G1 = B - iD
        grs[2] = g2r;      gis[2] = g2i;
        grs[3] = br - di;  gis[3] = bi + dr;   // G3 = B + iD
        #pragma unroll
        for (int j = 0; j < 4; j++) {
            ulonglong2 e = *(const ulonglong2*)&TWB[idx[j]][0];
            fma2(accB[j], pk2(grs[j], grs[j]), e.x);
            fma2(accC[j], pk2(gis[j], gis[j]), e.y);
            idx[j] = (idx[j] + kxv[j]) & 127;
        }
    }
    int b = blockIdx.x >> 6, t = blockIdx.x & 63;
    #pragma unroll
    for (int j = 0; j < 4; j++) {
        int m = (kxg * 4 + j) * 16 + ky;
        ull r = add2(accB[j], accC[j]);
        float re, im; upk2(r, re, im);
        g_Xf[m * 1024 + t * 16 + b] = make_float2(re, im);
    }
}

// ---------------------------------------------------------------------------
// K2: mode mixing. grid = 512, 256 threads. b in lanes -> weights broadcast.
// (exact R8)
// ---------------------------------------------------------------------------
__global__ void __launch_bounds__(256) k_modes() {
    extern __shared__ __align__(16) char sm2[];
    ulonglong2* Wsp = (ulonglong2*)sm2;                          // [64 t][65]
    ulonglong2* Xsm = (ulonglong2*)(sm2 + 64 * 65 * 16);         // [64 t][16 b]
    ull*        Ys2 = (ull*)(sm2 + 64 * 65 * 16 + 64 * 16 * 16); // [1024]

    int m = blockIdx.x, tid = threadIdx.x;

    #pragma unroll
    for (int p = 0; p < 16; p++) {
        int i = tid + p * 256;
        float2 w = g_W[(size_t)m * 4096 + i];
        Wsp[(i & 63) * 65 + (i >> 6)] = make_ulonglong2(pk2(w.x, w.x), pk2(w.y, w.y));
    }
    #pragma unroll
    for (int p = 0; p < 4; p++) {
        int i = tid + p * 256;
        float2 x = g_Xf[m * 1024 + i];
        Xsm[i] = make_ulonglong2(pk2(x.x, x.y), pk2(-x.y, x.x));
    }
    __syncthreads();

    int b = tid & 15, cq = tid >> 4;
    ull acc[4] = {0, 0, 0, 0};
    for (int t = 0; t < 64; t++) {
        ulonglong2 xv = Xsm[t * 16 + b];
        #pragma unroll
        for (int j = 0; j < 4; j++) {
            ulonglong2 wv = Wsp[t * 65 + cq * 4 + j];
            fma2(acc[j], wv.x, xv.x);
            fma2(acc[j], wv.y, xv.y);
        }
    }
    #pragma unroll
    for (int j = 0; j < 4; j++) Ys2[b * 64 + cq * 4 + j] = acc[j];
    __syncthreads();
    #pragma unroll
    for (int p = 0; p < 4; p++) {
        int i = tid + p * 256;
        *(ull*)&g_Y[(size_t)m * 1024 + i] = Ys2[i];
    }
}

// ---------------------------------------------------------------------------
// K3: inverse. grid = 1024 blocks, 256 threads, <=64 regs -> 4 blocks/SM.
// Phase A: radix-4 kx-fold (kx mod 4 classes, i^kx ladder). Phase B: exact R8.
// ---------------------------------------------------------------------------
__global__ void __launch_bounds__(256, 4) k_inverse(float* __restrict__ out) {
    __shared__ __align__(16) ull TWI[128][2];       // (c,s),(-s,c) — 2KB
    __shared__ ull Ysm[512];                        // 4KB
    __shared__ __align__(16) ulonglong2 ZZ[64][17]; // [(zr_h,zr_h64),(zi_h,zi_h64)]

    int tid = threadIdx.x;
    if (tid < 128) {
        float s, c; sincosf(PI2_OVER_128 * (float)tid, &s, &c);
        TWI[tid][0] = pk2(c, s);
        TWI[tid][1] = pk2(-s, c);
    }
    int off = blockIdx.x;   // b*64 + c
    Ysm[tid]       = *(const ull*)&g_Y[(size_t)tid * 1024 + off];
    Ysm[tid + 256] = *(const ull*)&g_Y[(size_t)(tid + 256) * 1024 + off];
    __syncthreads();

    // Phase A (radix-4 in kx): per h-base, class sums S_c = sum_{kx≡c(4)} Y e^{ikxhθ}.
    // Z[h]    = (S0+S2)+(S1+S3)      Z[h+64] = (S0+S2)-(S1+S3)
    // Z[h+32] = (S0-S2)+i(S1-S3)     Z[h+96] = (S0-S2)-i(S1-S3)
    // Thread: bases {hq, hq+16}, hq in 0..15. 8 accumulator ulls (16 regs).
    {
        int ky = tid & 15, hq = tid >> 4;
        ull S0[2] = {0, 0}, S1[2] = {0, 0}, S2[2] = {0, 0}, S3[2] = {0, 0};
        int hb[2] = {hq, hq + 16};
        int idx[2] = {0, 0};

        #pragma unroll
        for (int kxI = 0; kxI < 16; kxI++) {       // kx = kxI (kx mod 4 = kxI mod 4)
            float yr, yi; upk2(Ysm[kxI * 16 + ky], yr, yi);
            ull yrr = pk2(yr, yr), yii = pk2(yi, yi);
            #pragma unroll
            for (int u = 0; u < 2; u++) {
                ulonglong2 e = *(const ulonglong2*)&TWI[idx[u]][0];
                switch (kxI & 3) {
                    case 0:  fma2(S0[u], yrr, e.x); fma2(S0[u], yii, e.y); break;
                    case 1:  fma2(S1[u], yrr, e.x); fma2(S1[u], yii, e.y); break;
                    case 2:  fma2(S2[u], yrr, e.x); fma2(S2[u], yii, e.y); break;
                    default: fma2(S3[u], yrr, e.x); fma2(S3[u], yii, e.y); break;
                }
                idx[u] = (idx[u] + hb[u]) & 127;
            }
        }
        #pragma unroll
        for (int u = 0; u < 2; u++) idx[u] = (112 * hb[u]) & 127;
        #pragma unroll
        for (int kxI = 16; kxI < 32; kxI++) {      // kx = 96+kxI; 96≡0 (mod 4)
            float yr, yi; upk2(Ysm[kxI * 16 + ky], yr, yi);
            ull yrr = pk2(yr, yr), yii = pk2(yi, yi);
            #pragma unroll
            for (int u = 0; u < 2; u++) {
                ulonglong2 e = *(const ulonglong2*)&TWI[idx[u]][0];
                switch (kxI & 3) {
                    case 0:  fma2(S0[u], yrr, e.x); fma2(S0[u], yii, e.y); break;
                    case 1:  fma2(S1[u], yrr, e.x); fma2(S1[u], yii, e.y); break;
                    case 2:  fma2(S2[u], yrr, e.x); fma2(S2[u], yii, e.y); break;
                    default: fma2(S3[u], yrr, e.x); fma2(S3[u], yii, e.y); break;
                }
                idx[u] = (idx[u] + hb[u]) & 127;
            }
        }
        #pragma unroll
        for (int u = 0; u < 2; u++) {
            int r = hb[u];
            ull P  = add2(S0[u], S2[u]), Q  = sub2(S0[u], S2[u]);
            ull Tp = add2(S1[u], S3[u]), Tm = sub2(S1[u], S3[u]);
            ull Zh   = add2(P, Tp);     // Z[r]
            ull Zh64 = sub2(P, Tp);     // Z[r+64]
            float tr, ti_; upk2(Tm, tr, ti_);
            ull iTm = pk2(-ti_, tr);    // i*(S1-S3)
            ull Zh32 = add2(Q, iTm);    // Z[r+32]
            ull Zh96 = sub2(Q, iTm);    // Z[r+96]
            float ar_, ai_, br_, bi_;
            upk2(Zh, ar_, ai_); upk2(Zh64, br_, bi_);
            ZZ[r][ky] = make_ulonglong2(pk2(ar_, br_), pk2(ai_, bi_));
            upk2(Zh32, ar_, ai_); upk2(Zh96, br_, bi_);
            ZZ[r + 32][ky] = make_ulonglong2(pk2(ar_, br_), pk2(ai_, bi_));
        }
    }
    __syncthreads();

    // Phase B: out[r,wl] = accE+accO, out[r,wl+64] = accE-accO (ky parity fold).
    // EXACT R8 shape — do not touch (register knife-edge).
    int wl = tid & 63, rg = tid >> 6;      // rg in 0..3
    float* op = out + (size_t)blockIdx.x * 16384;
    #pragma unroll 1
    for (int pass = 0; pass < 2; pass++) {
        int r0 = rg * 16 + pass * 8;
        ull accE[8], accO[8];
        #pragma unroll
        for (int i = 0; i < 8; i++) {
            accE[i] = ZZ[r0 + i][0].x;     // ky=0: Re(Z0), weight 1
            accO[i] = 0;
        }
        #pragma unroll
        for (int k = 1; k < 16; k++) {
            float c, s; upk2(TWI[(k * wl) & 127][0], c, s);
            ull tcp = pk2(2.f * c, 2.f * c);
            ull tsp = pk2(-2.f * s, -2.f * s);
            if (k & 1) {
                #pragma unroll
                for (int i = 0; i < 8; i++) {
                    ulonglong2 zz = ZZ[r0 + i][k];
                    fma2(accO[i], zz.x, tcp);
                    fma2(accO[i], zz.y, tsp);
                }
            } else {
                #pragma unroll
                for (int i = 0; i < 8; i++) {
                    ulonglong2 zz = ZZ[r0 + i][k];
                    fma2(accE[i], zz.x, tcp);
                    fma2(accE[i], zz.y, tsp);
                }
            }
        }
        #pragma unroll
        for (int i = 0; i < 8; i++) {
            int r = r0 + i;
            ull olo = add2(accE[i], accO[i]);   // w = wl
            ull ohi = sub2(accE[i], accO[i]);   // w = wl + 64
            float a0, a1, b0, b1;
            upk2(olo, a0, a1);                  // (h=r, h=r+64)
            upk2(ohi, b0, b1);
            op[r * 128 + wl]             = a0;
            op[(r + 64) * 128 + wl]      = a1;
            op[r * 128 + wl + 64]        = b0;
            op[(r + 64) * 128 + wl + 64] = b1;
        }
    }
}

// ---------------------------------------------------------------------------
extern "C" void kernel_launch(void* const* d_in, const int* in_sizes, int n_in,
                              void* d_out, int out_size) {
    const float* X   = (const float*)d_in[0];
    const float* w0r = (const float*)d_in[1];
    const float* w0i = (const float*)d_in[2];
    const float* w1r = (const float*)d_in[3];
    const float* w1i = (const float*)d_in[4];
    float* out = (float*)d_out;

    static bool attr_done = false;
    if (!attr_done) {
        cudaFuncSetAttribute(k_modes, cudaFuncAttributeMaxDynamicSharedMemorySize,
                             91136);
        attr_done = true;
    }

    k_transpose<<<2048, 256>>>(w0r, w0i, w1r, w1i);
    k_forward<<<1024, 128>>>(X);
    k_modes<<<512, 256, 91136>>>();
    k_inverse<<<1024, 256>>>(out);
}